// round 1
// baseline (speedup 1.0000x reference)
#include <cuda_runtime.h>
#include <cuda_bf16.h>
#include <math.h>

// Problem constants
#define Bv 8
#define Tv 1024
#define Ev 1024
#define Hv 16
#define HDv 64
#define FFv 4096
#define Mv (Bv * Tv)   // 8192 rows

// ---------------------------------------------------------------------------
// Scratch (device globals; no runtime allocation allowed)
// ---------------------------------------------------------------------------
__device__ float g_qkv[(size_t)Mv * 3 * Ev];   // [8192, 3072]
__device__ float g_attn[(size_t)Mv * Ev];      // attention output
__device__ float g_y1[(size_t)Mv * Ev];        // residual + out-proj (pre-LN1)
__device__ float g_x1[(size_t)Mv * Ev];        // post-LN1
__device__ float g_h[(size_t)Mv * FFv];        // relu(fc1)
__device__ float g_y2[(size_t)Mv * Ev];        // pre-LN2
__device__ int   g_len[Bv];                    // per-batch valid length

// ---------------------------------------------------------------------------
// Padding-mask parsing: detect dtype (1-byte bool/u8 vs 4-byte int32/float32)
// then compute lengths[b] = count of "false" entries (mask is t >= length).
// ---------------------------------------------------------------------------
__global__ void len_kernel(const unsigned char* __restrict__ raw)
{
    __shared__ int sh_off, sh_f32;
    const int tid = threadIdx.x;
    if (tid == 0) { sh_off = 0; sh_f32 = 0; }
    __syncthreads();

    int f_off = 0, f_f32 = 0;
    for (int i = tid; i < Bv * Tv; i += 256) {   // first 8192 bytes (safe in all cases)
        unsigned char c = raw[i];
        if (c) {
            if ((i & 3) == 3 && c == 0x3f) f_f32 = 1;   // float 1.0f high byte
            else if ((i & 3) != 0) f_off = 1;           // nonzero off word boundary
        }
    }
    if (f_off) atomicOr(&sh_off, 1);
    if (f_f32) atomicOr(&sh_f32, 1);
    __syncthreads();

    // word_mode: elements are 4-byte (int32 or float32); test word != 0.
    // byte_mode: elements are 1-byte bool/u8.
    const bool byte_mode = (sh_f32 == 0) && (sh_off != 0);

    const int w = tid >> 5, lane = tid & 31;
    if (w < Bv) {
        int cnt = 0;
        for (int t = lane; t < Tv; t += 32) {
            int m;
            if (byte_mode) m = (int)raw[w * Tv + t];
            else           m = ((const int*)raw)[w * Tv + t];   // works for i32 & f32 bits
            cnt += (m == 0) ? 1 : 0;
        }
#pragma unroll
        for (int off = 16; off > 0; off >>= 1)
            cnt += __shfl_xor_sync(0xffffffffu, cnt, off);
        if (lane == 0) g_len[w] = cnt;
    }
}

// ---------------------------------------------------------------------------
// SGEMM:  C[M,N] = A[M,K] @ W[N,K]^T + bias[N]  (+ Res)  (ReLU optional)
// BM=BN=128, BK=16, 256 threads, 8x8 microtile. All dims divisible; no guards.
// ---------------------------------------------------------------------------
template<bool ADD_RES, bool RELU>
__global__ __launch_bounds__(256, 2) void sgemm_nt(
    const float* __restrict__ A, const float* __restrict__ W,
    const float* __restrict__ bias, const float* __restrict__ Res,
    float* __restrict__ C, int M, int N, int K)
{
    __shared__ float As[16][132];
    __shared__ float Bs[16][132];
    const int tid = threadIdx.x;
    const int tx = tid & 15;
    const int ty = tid >> 4;
    const int m0 = blockIdx.y * 128;
    const int n0 = blockIdx.x * 128;

    float acc[8][8];
#pragma unroll
    for (int i = 0; i < 8; i++)
#pragma unroll
        for (int j = 0; j < 8; j++) acc[i][j] = 0.f;

    for (int k0 = 0; k0 < K; k0 += 16) {
#pragma unroll
        for (int u = 0; u < 2; u++) {
            int id = tid + u * 256;          // 512 float4 per operand tile
            int r  = id >> 2;                // 0..127
            int kk = (id & 3) << 2;          // 0,4,8,12
            float4 a = *(const float4*)(A + (long)(m0 + r) * K + k0 + kk);
            As[kk + 0][r] = a.x; As[kk + 1][r] = a.y;
            As[kk + 2][r] = a.z; As[kk + 3][r] = a.w;
            float4 b = *(const float4*)(W + (long)(n0 + r) * K + k0 + kk);
            Bs[kk + 0][r] = b.x; Bs[kk + 1][r] = b.y;
            Bs[kk + 2][r] = b.z; Bs[kk + 3][r] = b.w;
        }
        __syncthreads();
#pragma unroll
        for (int k = 0; k < 16; k++) {
            float a[8], b[8];
            *(float4*)&a[0] = *(const float4*)&As[k][ty * 8];
            *(float4*)&a[4] = *(const float4*)&As[k][ty * 8 + 4];
            *(float4*)&b[0] = *(const float4*)&Bs[k][tx * 8];
            *(float4*)&b[4] = *(const float4*)&Bs[k][tx * 8 + 4];
#pragma unroll
            for (int i = 0; i < 8; i++)
#pragma unroll
                for (int j = 0; j < 8; j++)
                    acc[i][j] = fmaf(a[i], b[j], acc[i][j]);
        }
        __syncthreads();
    }

    const int n = n0 + tx * 8;
    float bvals[8];
    *(float4*)&bvals[0] = *(const float4*)(bias + n);
    *(float4*)&bvals[4] = *(const float4*)(bias + n + 4);
#pragma unroll
    for (int i = 0; i < 8; i++) {
        const long m = m0 + ty * 8 + i;
        float c[8];
#pragma unroll
        for (int j = 0; j < 8; j++) c[j] = acc[i][j] + bvals[j];
        if (ADD_RES) {
            float4 r0 = *(const float4*)(Res + m * N + n);
            float4 r1 = *(const float4*)(Res + m * N + n + 4);
            c[0] += r0.x; c[1] += r0.y; c[2] += r0.z; c[3] += r0.w;
            c[4] += r1.x; c[5] += r1.y; c[6] += r1.z; c[7] += r1.w;
        }
        if (RELU) {
#pragma unroll
            for (int j = 0; j < 8; j++) c[j] = fmaxf(c[j], 0.f);
        }
        *(float4*)(C + m * N + n)     = make_float4(c[0], c[1], c[2], c[3]);
        *(float4*)(C + m * N + n + 4) = make_float4(c[4], c[5], c[6], c[7]);
    }
}

// ---------------------------------------------------------------------------
// Fused attention: one block per (b, h, 64-row q tile). Online softmax.
// smem: Qt[64][68] (d-major), KtP[64][68] (K d-major, then P q-major),
//       Vs[64][64] (k-major), row stats m/l.
// ---------------------------------------------------------------------------
#define ATT_SMEM ((2 * 64 * 68 + 64 * 64 + 128) * 4)

__global__ __launch_bounds__(256) void attn_kernel(const float* __restrict__ qkv,
                                                   float* __restrict__ out)
{
    extern __shared__ float sm[];
    float* Qt  = sm;                       // [64][68]
    float* KtP = sm + 64 * 68;             // [64][68]
    float* Vs  = sm + 2 * 64 * 68;         // [64][64]
    float* smM = sm + 2 * 64 * 68 + 64 * 64;
    float* smL = smM + 64;

    const int b = blockIdx.z, h = blockIdx.y, qt = blockIdx.x;
    const int tid = threadIdx.x;
    const int tx = tid & 15, ty = tid >> 4;
    const int len = g_len[b];
    const int q0 = qt * 64;
    const long base = (long)b * Tv * (3 * Ev);

    // Load Q tile (scaled by HD^-0.5 = 0.125), transposed to d-major
#pragma unroll
    for (int u = 0; u < 4; u++) {
        int id = tid + u * 256;
        int r = id >> 4;
        int d4 = (id & 15) << 2;
        float4 v = *(const float4*)(qkv + base + (long)(q0 + r) * (3 * Ev) + h * HDv + d4);
        Qt[(d4 + 0) * 68 + r] = v.x * 0.125f;
        Qt[(d4 + 1) * 68 + r] = v.y * 0.125f;
        Qt[(d4 + 2) * 68 + r] = v.z * 0.125f;
        Qt[(d4 + 3) * 68 + r] = v.w * 0.125f;
    }
    if (tid < 64) { smM[tid] = -1e30f; smL[tid] = 0.f; }

    float o[4][4];
#pragma unroll
    for (int i = 0; i < 4; i++)
#pragma unroll
        for (int j = 0; j < 4; j++) o[i][j] = 0.f;

    const int ktend = min(qt, (len + 63) / 64 - 1);
    for (int kt = 0; kt <= ktend; kt++) {
        __syncthreads();   // prev iteration done with KtP/Vs; Qt/stats visible
#pragma unroll
        for (int u = 0; u < 4; u++) {
            int id = tid + u * 256;
            int r = id >> 4;
            int d4 = (id & 15) << 2;
            long rowb = base + (long)(kt * 64 + r) * (3 * Ev) + h * HDv + d4;
            float4 kv = *(const float4*)(qkv + rowb + Ev);
            KtP[(d4 + 0) * 68 + r] = kv.x;
            KtP[(d4 + 1) * 68 + r] = kv.y;
            KtP[(d4 + 2) * 68 + r] = kv.z;
            KtP[(d4 + 3) * 68 + r] = kv.w;
            float4 vv = *(const float4*)(qkv + rowb + 2 * Ev);
            *(float4*)&Vs[r * 64 + d4] = vv;
        }
        __syncthreads();

        // GEMM1: S = Q @ K^T  (thread owns S[4q][4k])
        float s[4][4];
#pragma unroll
        for (int i = 0; i < 4; i++)
#pragma unroll
            for (int j = 0; j < 4; j++) s[i][j] = 0.f;
#pragma unroll
        for (int d = 0; d < 64; d++) {
            float4 aq = *(const float4*)&Qt[d * 68 + ty * 4];
            float4 bk = *(const float4*)&KtP[d * 68 + tx * 4];
            float av[4] = {aq.x, aq.y, aq.z, aq.w};
            float bv[4] = {bk.x, bk.y, bk.z, bk.w};
#pragma unroll
            for (int i = 0; i < 4; i++)
#pragma unroll
                for (int j = 0; j < 4; j++)
                    s[i][j] = fmaf(av[i], bv[j], s[i][j]);
        }

        // Mask: causal (k > q) or key padding (k >= len)
#pragma unroll
        for (int i = 0; i < 4; i++) {
            int qg = q0 + ty * 4 + i;
#pragma unroll
            for (int j = 0; j < 4; j++) {
                int kg = kt * 64 + tx * 4 + j;
                if (kg > qg || kg >= len) s[i][j] = -1e30f;
            }
        }

        // Online softmax: per-row reductions across the 16-lane tx group
        float mnew[4], scl[4], rsum[4], p[4][4];
#pragma unroll
        for (int i = 0; i < 4; i++) {
            float rm = fmaxf(fmaxf(s[i][0], s[i][1]), fmaxf(s[i][2], s[i][3]));
            rm = fmaxf(rm, __shfl_xor_sync(0xffffffffu, rm, 1));
            rm = fmaxf(rm, __shfl_xor_sync(0xffffffffu, rm, 2));
            rm = fmaxf(rm, __shfl_xor_sync(0xffffffffu, rm, 4));
            rm = fmaxf(rm, __shfl_xor_sync(0xffffffffu, rm, 8));
            float mold = smM[ty * 4 + i];
            float mn = fmaxf(mold, rm);
            mnew[i] = mn;
            scl[i] = __expf(mold - mn);
            float rs = 0.f;
#pragma unroll
            for (int j = 0; j < 4; j++) { p[i][j] = __expf(s[i][j] - mn); rs += p[i][j]; }
            rs += __shfl_xor_sync(0xffffffffu, rs, 1);
            rs += __shfl_xor_sync(0xffffffffu, rs, 2);
            rs += __shfl_xor_sync(0xffffffffu, rs, 4);
            rs += __shfl_xor_sync(0xffffffffu, rs, 8);
            rsum[i] = rs;
        }
        if (tx == 0) {
#pragma unroll
            for (int i = 0; i < 4; i++) {
                smM[ty * 4 + i] = mnew[i];
                smL[ty * 4 + i] = smL[ty * 4 + i] * scl[i] + rsum[i];
            }
        }
#pragma unroll
        for (int i = 0; i < 4; i++)
#pragma unroll
            for (int j = 0; j < 4; j++) o[i][j] *= scl[i];

        __syncthreads();   // all warps done reading K from KtP
        // Write P (q-major) into the K buffer
#pragma unroll
        for (int i = 0; i < 4; i++)
            *(float4*)&KtP[(ty * 4 + i) * 68 + tx * 4] =
                make_float4(p[i][0], p[i][1], p[i][2], p[i][3]);
        __syncthreads();

        // GEMM2: O += P @ V  (thread owns O[4q][4d])
#pragma unroll
        for (int k = 0; k < 64; k++) {
            float a0 = KtP[(ty * 4 + 0) * 68 + k];
            float a1 = KtP[(ty * 4 + 1) * 68 + k];
            float a2 = KtP[(ty * 4 + 2) * 68 + k];
            float a3 = KtP[(ty * 4 + 3) * 68 + k];
            float4 bv = *(const float4*)&Vs[k * 64 + tx * 4];
            o[0][0] = fmaf(a0, bv.x, o[0][0]); o[0][1] = fmaf(a0, bv.y, o[0][1]);
            o[0][2] = fmaf(a0, bv.z, o[0][2]); o[0][3] = fmaf(a0, bv.w, o[0][3]);
            o[1][0] = fmaf(a1, bv.x, o[1][0]); o[1][1] = fmaf(a1, bv.y, o[1][1]);
            o[1][2] = fmaf(a1, bv.z, o[1][2]); o[1][3] = fmaf(a1, bv.w, o[1][3]);
            o[2][0] = fmaf(a2, bv.x, o[2][0]); o[2][1] = fmaf(a2, bv.y, o[2][1]);
            o[2][2] = fmaf(a2, bv.z, o[2][2]); o[2][3] = fmaf(a2, bv.w, o[2][3]);
            o[3][0] = fmaf(a3, bv.x, o[3][0]); o[3][1] = fmaf(a3, bv.y, o[3][1]);
            o[3][2] = fmaf(a3, bv.z, o[3][2]); o[3][3] = fmaf(a3, bv.w, o[3][3]);
        }
    }
    __syncthreads();

#pragma unroll
    for (int i = 0; i < 4; i++) {
        float inv = 1.f / smL[ty * 4 + i];
        long row = (long)b * Tv + q0 + ty * 4 + i;
        float4 r = make_float4(o[i][0] * inv, o[i][1] * inv, o[i][2] * inv, o[i][3] * inv);
        *(float4*)(out + row * Ev + h * HDv + tx * 4) = r;
    }
}

// ---------------------------------------------------------------------------
// LayerNorm over E=1024 (one block per row, 256 threads, float4)
// ---------------------------------------------------------------------------
__global__ __launch_bounds__(256) void ln_kernel(const float* __restrict__ X,
                                                 const float* __restrict__ w,
                                                 const float* __restrict__ bvec,
                                                 float* __restrict__ out)
{
    const int row = blockIdx.x;
    const int tid = threadIdx.x;
    const float4 v = *(const float4*)(X + (long)row * Ev + tid * 4);
    float s = v.x + v.y + v.z + v.w;
    float q = v.x * v.x + v.y * v.y + v.z * v.z + v.w * v.w;
#pragma unroll
    for (int off = 16; off > 0; off >>= 1) {
        s += __shfl_xor_sync(0xffffffffu, s, off);
        q += __shfl_xor_sync(0xffffffffu, q, off);
    }
    __shared__ float red[16];
    __shared__ float sh_u, sh_r;
    const int wid = tid >> 5, lane = tid & 31;
    if (lane == 0) { red[wid] = s; red[8 + wid] = q; }
    __syncthreads();
    if (tid == 0) {
        float S = 0.f, Q = 0.f;
#pragma unroll
        for (int i = 0; i < 8; i++) { S += red[i]; Q += red[8 + i]; }
        float u = S * (1.f / 1024.f);
        float var = fmaxf(Q * (1.f / 1024.f) - u * u, 0.f);
        sh_u = u;
        sh_r = rsqrtf(var + 1e-12f);
    }
    __syncthreads();
    const float u = sh_u, rstd = sh_r;
    float4 ww = *(const float4*)(w + tid * 4);
    float4 bb = *(const float4*)(bvec + tid * 4);
    float4 o;
    o.x = (v.x - u) * rstd * ww.x + bb.x;
    o.y = (v.y - u) * rstd * ww.y + bb.y;
    o.z = (v.z - u) * rstd * ww.z + bb.z;
    o.w = (v.w - u) * rstd * ww.w + bb.w;
    *(float4*)(out + (long)row * Ev + tid * 4) = o;
}

// ---------------------------------------------------------------------------
// Launch
// ---------------------------------------------------------------------------
extern "C" void kernel_launch(void* const* d_in, const int* in_sizes, int n_in,
                              void* d_out, int out_size)
{
    const float* x     = (const float*)d_in[0];
    const float* in_w  = (const float*)d_in[1];
    const float* in_b  = (const float*)d_in[2];
    const float* out_w = (const float*)d_in[3];
    const float* out_b = (const float*)d_in[4];
    const float* fc1_w = (const float*)d_in[5];
    const float* fc1_b = (const float*)d_in[6];
    const float* fc2_w = (const float*)d_in[7];
    const float* fc2_b = (const float*)d_in[8];
    const float* ln1_w = (const float*)d_in[9];
    const float* ln1_b = (const float*)d_in[10];
    const float* ln2_w = (const float*)d_in[11];
    const float* ln2_b = (const float*)d_in[12];

    // Padding mask is the unique input with B*T = 8192 elements.
    const unsigned char* pmask = (const unsigned char*)d_in[13];
    for (int i = 0; i < n_in; i++)
        if (in_sizes[i] == Bv * Tv) { pmask = (const unsigned char*)d_in[i]; break; }

    float *qkv, *attn, *y1, *x1, *hb, *y2;
    cudaGetSymbolAddress((void**)&qkv,  g_qkv);
    cudaGetSymbolAddress((void**)&attn, g_attn);
    cudaGetSymbolAddress((void**)&y1,   g_y1);
    cudaGetSymbolAddress((void**)&x1,   g_x1);
    cudaGetSymbolAddress((void**)&hb,   g_h);
    cudaGetSymbolAddress((void**)&y2,   g_y2);

    cudaFuncSetAttribute(attn_kernel, cudaFuncAttributeMaxDynamicSharedMemorySize, ATT_SMEM);

    len_kernel<<<1, 256>>>(pmask);

    // QKV projection: [8192,1024] @ [3072,1024]^T
    sgemm_nt<false, false><<<dim3(3 * Ev / 128, Mv / 128), 256>>>(
        x, in_w, in_b, nullptr, qkv, Mv, 3 * Ev, Ev);

    // Fused causal attention (+ key padding)
    attn_kernel<<<dim3(Tv / 64, Hv, Bv), 256, ATT_SMEM>>>(qkv, attn);

    // Out projection + residual
    sgemm_nt<true, false><<<dim3(Ev / 128, Mv / 128), 256>>>(
        attn, out_w, out_b, x, y1, Mv, Ev, Ev);
    ln_kernel<<<Mv, 256>>>(y1, ln1_w, ln1_b, x1);

    // FFN
    sgemm_nt<false, true><<<dim3(FFv / 128, Mv / 128), 256>>>(
        x1, fc1_w, fc1_b, nullptr, hb, Mv, FFv, Ev);
    sgemm_nt<true, false><<<dim3(Ev / 128, Mv / 128), 256>>>(
        hb, fc2_w, fc2_b, x1, y2, Mv, Ev, FFv);
    ln_kernel<<<Mv, 256>>>(y2, ln2_w, ln2_b, (float*)d_out);

    (void)in_sizes; (void)n_in; (void)out_size;
}

// round 5
// speedup vs baseline: 2.5965x; 2.5965x over previous
#include <cuda_runtime.h>
#include <cuda_bf16.h>
#include <math.h>
#include <stdint.h>

// Problem constants
#define Bv 8
#define Tv 1024
#define Ev 1024
#define Hv 16
#define HDv 64
#define FFv 4096
#define Mv (Bv * Tv)   // 8192 rows

// ---------------------------------------------------------------------------
// Scratch (device globals; no runtime allocation allowed)
// ---------------------------------------------------------------------------
__device__ float g_qkv[(size_t)Mv * 3 * Ev];
__device__ float g_attn[(size_t)Mv * Ev];
__device__ float g_y1[(size_t)Mv * Ev];
__device__ float g_x1[(size_t)Mv * Ev];
__device__ float g_h[(size_t)Mv * FFv];
__device__ float g_y2[(size_t)Mv * Ev];
__device__ int   g_len[Bv];

// ---------------------------------------------------------------------------
// Helpers
// ---------------------------------------------------------------------------
__device__ __forceinline__ uint32_t smem_u32(const void* p) {
    uint32_t a;
    asm("{ .reg .u64 t; cvta.to.shared.u64 t, %1; cvt.u32.u64 %0, t; }" : "=r"(a) : "l"(p));
    return a;
}
__device__ __forceinline__ void cp16(uint32_t dst, const void* src) {
    asm volatile("cp.async.cg.shared.global [%0], [%1], 16;" :: "r"(dst), "l"(src));
}
__device__ __forceinline__ uint32_t f2tf(float f) {
    uint32_t r;
    asm("cvt.rna.tf32.f32 %0, %1;" : "=r"(r) : "f"(f));
    return r;
}
__device__ __forceinline__ void mma_tf32(float* c, const uint32_t* a, const uint32_t* b) {
    asm volatile(
        "mma.sync.aligned.m16n8k8.row.col.f32.tf32.tf32.f32 "
        "{%0,%1,%2,%3}, {%4,%5,%6,%7}, {%8,%9}, {%0,%1,%2,%3};"
        : "+f"(c[0]), "+f"(c[1]), "+f"(c[2]), "+f"(c[3])
        : "r"(a[0]), "r"(a[1]), "r"(a[2]), "r"(a[3]), "r"(b[0]), "r"(b[1]));
}

// ---------------------------------------------------------------------------
// tf32 mma.sync GEMM:  C[M,N] = A[M,K] @ W[N,K]^T + bias (+Res) (ReLU)
// BM=BN=128, BK=32, 256 threads (8 warps, 2m x 4n, warp tile 64x32),
// 2-stage cp.async pipeline. smem rows padded to 36 floats (conflict-free).
// ---------------------------------------------------------------------------
#define BKg 32
#define ROWPAD 36                               // floats per smem row
#define TILE_FL (128 * ROWPAD)                  // 4608 floats per operand tile
#define STAGE_FL (2 * TILE_FL)                  // A then W
#define STAGE_BY (STAGE_FL * 4)                 // 36864 B
#define GSMEM (2 * STAGE_BY)                    // 73728 B

__device__ __forceinline__ void load_tiles_g(
    const float* __restrict__ A, const float* __restrict__ W, int K,
    int m0, int n0, int kc, uint32_t sbase, int tid)
{
#pragma unroll
    for (int i = 0; i < 4; i++) {               // A tile: 128 rows x 8 float4
        int idx = tid + i * 256;
        int r = idx >> 3, q = idx & 7;
        cp16(sbase + r * (ROWPAD * 4) + q * 16,
             A + (size_t)(m0 + r) * K + kc + q * 4);
    }
#pragma unroll
    for (int i = 0; i < 4; i++) {               // W tile
        int idx = tid + i * 256;
        int r = idx >> 3, q = idx & 7;
        cp16(sbase + TILE_FL * 4 + r * (ROWPAD * 4) + q * 16,
             W + (size_t)(n0 + r) * K + kc + q * 4);
    }
}

template<bool ADD_RES, bool RELU>
__global__ __launch_bounds__(256, 2) void mma_gemm(
    const float* __restrict__ A, const float* __restrict__ W,
    const float* __restrict__ bias, const float* __restrict__ Res,
    float* __restrict__ C, int M, int N, int K)
{
    extern __shared__ float smf[];
    const uint32_t sb = smem_u32(smf);
    const int tid = threadIdx.x;
    const int wid = tid >> 5, lid = tid & 31;
    const int wm = wid & 1, wn = wid >> 1;      // 2 x 4 warp grid
    const int g = lid >> 2, tg = lid & 3;
    const int m0 = blockIdx.y * 128, n0 = blockIdx.x * 128;

    float acc[4][4][4];
#pragma unroll
    for (int i = 0; i < 4; i++)
#pragma unroll
        for (int j = 0; j < 4; j++)
#pragma unroll
            for (int v = 0; v < 4; v++) acc[i][j][v] = 0.f;

    const int NC = K / BKg;
    load_tiles_g(A, W, K, m0, n0, 0, sb, tid);
    asm volatile("cp.async.commit_group;" ::: "memory");
    load_tiles_g(A, W, K, m0, n0, BKg, sb + STAGE_BY, tid);
    asm volatile("cp.async.commit_group;" ::: "memory");

    for (int c = 0; c < NC; c++) {
        const int s = c & 1;
        asm volatile("cp.async.wait_group %0;" :: "n"(1) : "memory");
        __syncthreads();
        const float* As = smf + s * STAGE_FL;
        const float* Ws = As + TILE_FL;

#pragma unroll
        for (int kk = 0; kk < 4; kk++) {
            const int k0 = kk * 8;
            uint32_t af[4][4];
#pragma unroll
            for (int i = 0; i < 4; i++) {
                int rb = wm * 64 + i * 16 + g;
                af[i][0] = f2tf(As[rb * ROWPAD + k0 + tg]);
                af[i][1] = f2tf(As[(rb + 8) * ROWPAD + k0 + tg]);
                af[i][2] = f2tf(As[rb * ROWPAD + k0 + tg + 4]);
                af[i][3] = f2tf(As[(rb + 8) * ROWPAD + k0 + tg + 4]);
            }
            uint32_t bf[4][2];
#pragma unroll
            for (int j = 0; j < 4; j++) {
                int nb = wn * 32 + j * 8 + g;
                bf[j][0] = f2tf(Ws[nb * ROWPAD + k0 + tg]);
                bf[j][1] = f2tf(Ws[nb * ROWPAD + k0 + tg + 4]);
            }
#pragma unroll
            for (int i = 0; i < 4; i++)
#pragma unroll
                for (int j = 0; j < 4; j++)
                    mma_tf32(acc[i][j], af[i], bf[j]);
        }
        __syncthreads();
        if (c + 2 < NC) {
            load_tiles_g(A, W, K, m0, n0, (c + 2) * BKg, sb + s * STAGE_BY, tid);
        }
        asm volatile("cp.async.commit_group;" ::: "memory");
    }

    // Epilogue: fragment (row = g/g+8, col = tg*2, tg*2+1) per 16x8 tile
#pragma unroll
    for (int i = 0; i < 4; i++) {
#pragma unroll
        for (int r = 0; r < 2; r++) {
            const size_t row = (size_t)(m0 + wm * 64 + i * 16 + g + r * 8);
#pragma unroll
            for (int j = 0; j < 4; j++) {
                const int col = n0 + wn * 32 + j * 8 + tg * 2;
                float2 o;
                o.x = acc[i][j][r * 2 + 0];
                o.y = acc[i][j][r * 2 + 1];
                const float2 bb = *(const float2*)(bias + col);
                o.x += bb.x; o.y += bb.y;
                if (ADD_RES) {
                    float2 rr = *(const float2*)(Res + row * N + col);
                    o.x += rr.x; o.y += rr.y;
                }
                if (RELU) { o.x = fmaxf(o.x, 0.f); o.y = fmaxf(o.y, 0.f); }
                *(float2*)(C + row * N + col) = o;
            }
        }
    }
}

// ---------------------------------------------------------------------------
// Padding-mask parsing (unchanged)
// ---------------------------------------------------------------------------
__global__ void len_kernel(const unsigned char* __restrict__ raw)
{
    __shared__ int sh_off, sh_f32;
    const int tid = threadIdx.x;
    if (tid == 0) { sh_off = 0; sh_f32 = 0; }
    __syncthreads();
    int f_off = 0, f_f32 = 0;
    for (int i = tid; i < Bv * Tv; i += 256) {
        unsigned char c = raw[i];
        if (c) {
            if ((i & 3) == 3 && c == 0x3f) f_f32 = 1;
            else if ((i & 3) != 0) f_off = 1;
        }
    }
    if (f_off) atomicOr(&sh_off, 1);
    if (f_f32) atomicOr(&sh_f32, 1);
    __syncthreads();
    const bool byte_mode = (sh_f32 == 0) && (sh_off != 0);
    const int w = tid >> 5, lane = tid & 31;
    if (w < Bv) {
        int cnt = 0;
        for (int t = lane; t < Tv; t += 32) {
            int m;
            if (byte_mode) m = (int)raw[w * Tv + t];
            else           m = ((const int*)raw)[w * Tv + t];
            cnt += (m == 0) ? 1 : 0;
        }
#pragma unroll
        for (int off = 16; off > 0; off >>= 1)
            cnt += __shfl_xor_sync(0xffffffffu, cnt, off);
        if (lane == 0) g_len[w] = cnt;
    }
}

// ---------------------------------------------------------------------------
// Fused attention (unchanged SIMT flash-style)
// ---------------------------------------------------------------------------
#define ATT_SMEM ((2 * 64 * 68 + 64 * 64 + 128) * 4)

__global__ __launch_bounds__(256) void attn_kernel(const float* __restrict__ qkv,
                                                   float* __restrict__ out)
{
    extern __shared__ float sm[];
    float* Qt  = sm;
    float* KtP = sm + 64 * 68;
    float* Vs  = sm + 2 * 64 * 68;
    float* smM = sm + 2 * 64 * 68 + 64 * 64;
    float* smL = smM + 64;

    const int b = blockIdx.z, h = blockIdx.y, qt = blockIdx.x;
    const int tid = threadIdx.x;
    const int tx = tid & 15, ty = tid >> 4;
    const int len = g_len[b];
    const int q0 = qt * 64;
    const long base = (long)b * Tv * (3 * Ev);

#pragma unroll
    for (int u = 0; u < 4; u++) {
        int id = tid + u * 256;
        int r = id >> 4;
        int d4 = (id & 15) << 2;
        float4 v = *(const float4*)(qkv + base + (long)(q0 + r) * (3 * Ev) + h * HDv + d4);
        Qt[(d4 + 0) * 68 + r] = v.x * 0.125f;
        Qt[(d4 + 1) * 68 + r] = v.y * 0.125f;
        Qt[(d4 + 2) * 68 + r] = v.z * 0.125f;
        Qt[(d4 + 3) * 68 + r] = v.w * 0.125f;
    }
    if (tid < 64) { smM[tid] = -1e30f; smL[tid] = 0.f; }

    float o[4][4];
#pragma unroll
    for (int i = 0; i < 4; i++)
#pragma unroll
        for (int j = 0; j < 4; j++) o[i][j] = 0.f;

    const int ktend = min(qt, (len + 63) / 64 - 1);
    for (int kt = 0; kt <= ktend; kt++) {
        __syncthreads();
#pragma unroll
        for (int u = 0; u < 4; u++) {
            int id = tid + u * 256;
            int r = id >> 4;
            int d4 = (id & 15) << 2;
            long rowb = base + (long)(kt * 64 + r) * (3 * Ev) + h * HDv + d4;
            float4 kv = *(const float4*)(qkv + rowb + Ev);
            KtP[(d4 + 0) * 68 + r] = kv.x;
            KtP[(d4 + 1) * 68 + r] = kv.y;
            KtP[(d4 + 2) * 68 + r] = kv.z;
            KtP[(d4 + 3) * 68 + r] = kv.w;
            float4 vv = *(const float4*)(qkv + rowb + 2 * Ev);
            *(float4*)&Vs[r * 64 + d4] = vv;
        }
        __syncthreads();

        float s[4][4];
#pragma unroll
        for (int i = 0; i < 4; i++)
#pragma unroll
            for (int j = 0; j < 4; j++) s[i][j] = 0.f;
#pragma unroll
        for (int d = 0; d < 64; d++) {
            float4 aq = *(const float4*)&Qt[d * 68 + ty * 4];
            float4 bk = *(const float4*)&KtP[d * 68 + tx * 4];
            float av[4] = {aq.x, aq.y, aq.z, aq.w};
            float bv[4] = {bk.x, bk.y, bk.z, bk.w};
#pragma unroll
            for (int i = 0; i < 4; i++)
#pragma unroll
                for (int j = 0; j < 4; j++)
                    s[i][j] = fmaf(av[i], bv[j], s[i][j]);
        }

#pragma unroll
        for (int i = 0; i < 4; i++) {
            int qg = q0 + ty * 4 + i;
#pragma unroll
            for (int j = 0; j < 4; j++) {
                int kg = kt * 64 + tx * 4 + j;
                if (kg > qg || kg >= len) s[i][j] = -1e30f;
            }
        }

        float mnew[4], scl[4], rsum[4], p[4][4];
#pragma unroll
        for (int i = 0; i < 4; i++) {
            float rm = fmaxf(fmaxf(s[i][0], s[i][1]), fmaxf(s[i][2], s[i][3]));
            rm = fmaxf(rm, __shfl_xor_sync(0xffffffffu, rm, 1));
            rm = fmaxf(rm, __shfl_xor_sync(0xffffffffu, rm, 2));
            rm = fmaxf(rm, __shfl_xor_sync(0xffffffffu, rm, 4));
            rm = fmaxf(rm, __shfl_xor_sync(0xffffffffu, rm, 8));
            float mold = smM[ty * 4 + i];
            float mn = fmaxf(mold, rm);
            mnew[i] = mn;
            scl[i] = __expf(mold - mn);
            float rs = 0.f;
#pragma unroll
            for (int j = 0; j < 4; j++) { p[i][j] = __expf(s[i][j] - mn); rs += p[i][j]; }
            rs += __shfl_xor_sync(0xffffffffu, rs, 1);
            rs += __shfl_xor_sync(0xffffffffu, rs, 2);
            rs += __shfl_xor_sync(0xffffffffu, rs, 4);
            rs += __shfl_xor_sync(0xffffffffu, rs, 8);
            rsum[i] = rs;
        }
        if (tx == 0) {
#pragma unroll
            for (int i = 0; i < 4; i++) {
                smM[ty * 4 + i] = mnew[i];
                smL[ty * 4 + i] = smL[ty * 4 + i] * scl[i] + rsum[i];
            }
        }
#pragma unroll
        for (int i = 0; i < 4; i++)
#pragma unroll
            for (int j = 0; j < 4; j++) o[i][j] *= scl[i];

        __syncthreads();
#pragma unroll
        for (int i = 0; i < 4; i++)
            *(float4*)&KtP[(ty * 4 + i) * 68 + tx * 4] =
                make_float4(p[i][0], p[i][1], p[i][2], p[i][3]);
        __syncthreads();

#pragma unroll
        for (int k = 0; k < 64; k++) {
            float a0 = KtP[(ty * 4 + 0) * 68 + k];
            float a1 = KtP[(ty * 4 + 1) * 68 + k];
            float a2 = KtP[(ty * 4 + 2) * 68 + k];
            float a3 = KtP[(ty * 4 + 3) * 68 + k];
            float4 bv = *(const float4*)&Vs[k * 64 + tx * 4];
            o[0][0] = fmaf(a0, bv.x, o[0][0]); o[0][1] = fmaf(a0, bv.y, o[0][1]);
            o[0][2] = fmaf(a0, bv.z, o[0][2]); o[0][3] = fmaf(a0, bv.w, o[0][3]);
            o[1][0] = fmaf(a1, bv.x, o[1][0]); o[1][1] = fmaf(a1, bv.y, o[1][1]);
            o[1][2] = fmaf(a1, bv.z, o[1][2]); o[1][3] = fmaf(a1, bv.w, o[1][3]);
            o[2][0] = fmaf(a2, bv.x, o[2][0]); o[2][1] = fmaf(a2, bv.y, o[2][1]);
            o[2][2] = fmaf(a2, bv.z, o[2][2]); o[2][3] = fmaf(a2, bv.w, o[2][3]);
            o[3][0] = fmaf(a3, bv.x, o[3][0]); o[3][1] = fmaf(a3, bv.y, o[3][1]);
            o[3][2] = fmaf(a3, bv.z, o[3][2]); o[3][3] = fmaf(a3, bv.w, o[3][3]);
        }
    }
    __syncthreads();

#pragma unroll
    for (int i = 0; i < 4; i++) {
        float inv = 1.f / smL[ty * 4 + i];
        long row = (long)b * Tv + q0 + ty * 4 + i;
        float4 r = make_float4(o[i][0] * inv, o[i][1] * inv, o[i][2] * inv, o[i][3] * inv);
        *(float4*)(out + row * Ev + h * HDv + tx * 4) = r;
    }
}

// ---------------------------------------------------------------------------
// LayerNorm (unchanged)
// ---------------------------------------------------------------------------
__global__ __launch_bounds__(256) void ln_kernel(const float* __restrict__ X,
                                                 const float* __restrict__ w,
                                                 const float* __restrict__ bvec,
                                                 float* __restrict__ out)
{
    const int row = blockIdx.x;
    const int tid = threadIdx.x;
    const float4 v = *(const float4*)(X + (long)row * Ev + tid * 4);
    float s = v.x + v.y + v.z + v.w;
    float q = v.x * v.x + v.y * v.y + v.z * v.z + v.w * v.w;
#pragma unroll
    for (int off = 16; off > 0; off >>= 1) {
        s += __shfl_xor_sync(0xffffffffu, s, off);
        q += __shfl_xor_sync(0xffffffffu, q, off);
    }
    __shared__ float red[16];
    __shared__ float sh_u, sh_r;
    const int wid = tid >> 5, lane = tid & 31;
    if (lane == 0) { red[wid] = s; red[8 + wid] = q; }
    __syncthreads();
    if (tid == 0) {
        float S = 0.f, Q = 0.f;
#pragma unroll
        for (int i = 0; i < 8; i++) { S += red[i]; Q += red[8 + i]; }
        float u = S * (1.f / 1024.f);
        float var = fmaxf(Q * (1.f / 1024.f) - u * u, 0.f);
        sh_u = u;
        sh_r = rsqrtf(var + 1e-12f);
    }
    __syncthreads();
    const float u = sh_u, rstd = sh_r;
    float4 ww = *(const float4*)(w + tid * 4);
    float4 bb = *(const float4*)(bvec + tid * 4);
    float4 o;
    o.x = (v.x - u) * rstd * ww.x + bb.x;
    o.y = (v.y - u) * rstd * ww.y + bb.y;
    o.z = (v.z - u) * rstd * ww.z + bb.z;
    o.w = (v.w - u) * rstd * ww.w + bb.w;
    *(float4*)(out + (long)row * Ev + tid * 4) = o;
}

// ---------------------------------------------------------------------------
// Launch
// ---------------------------------------------------------------------------
extern "C" void kernel_launch(void* const* d_in, const int* in_sizes, int n_in,
                              void* d_out, int out_size)
{
    const float* x     = (const float*)d_in[0];
    const float* in_w  = (const float*)d_in[1];
    const float* in_b  = (const float*)d_in[2];
    const float* out_w = (const float*)d_in[3];
    const float* out_b = (const float*)d_in[4];
    const float* fc1_w = (const float*)d_in[5];
    const float* fc1_b = (const float*)d_in[6];
    const float* fc2_w = (const float*)d_in[7];
    const float* fc2_b = (const float*)d_in[8];
    const float* ln1_w = (const float*)d_in[9];
    const float* ln1_b = (const float*)d_in[10];
    const float* ln2_w = (const float*)d_in[11];
    const float* ln2_b = (const float*)d_in[12];

    const unsigned char* pmask = (const unsigned char*)d_in[13];
    for (int i = 0; i < n_in; i++)
        if (in_sizes[i] == Bv * Tv) { pmask = (const unsigned char*)d_in[i]; break; }

    float *qkv, *attn, *y1, *x1, *hb, *y2;
    cudaGetSymbolAddress((void**)&qkv,  g_qkv);
    cudaGetSymbolAddress((void**)&attn, g_attn);
    cudaGetSymbolAddress((void**)&y1,   g_y1);
    cudaGetSymbolAddress((void**)&x1,   g_x1);
    cudaGetSymbolAddress((void**)&hb,   g_h);
    cudaGetSymbolAddress((void**)&y2,   g_y2);

    cudaFuncSetAttribute(attn_kernel, cudaFuncAttributeMaxDynamicSharedMemorySize, ATT_SMEM);
    cudaFuncSetAttribute(mma_gemm<false, false>, cudaFuncAttributeMaxDynamicSharedMemorySize, GSMEM);
    cudaFuncSetAttribute(mma_gemm<true,  false>, cudaFuncAttributeMaxDynamicSharedMemorySize, GSMEM);
    cudaFuncSetAttribute(mma_gemm<false, true >, cudaFuncAttributeMaxDynamicSharedMemorySize, GSMEM);

    len_kernel<<<1, 256>>>(pmask);

    // QKV projection: [8192,1024] @ [3072,1024]^T
    mma_gemm<false, false><<<dim3(3 * Ev / 128, Mv / 128), 256, GSMEM>>>(
        x, in_w, in_b, nullptr, qkv, Mv, 3 * Ev, Ev);

    // Fused causal attention (+ key padding)
    attn_kernel<<<dim3(Tv / 64, Hv, Bv), 256, ATT_SMEM>>>(qkv, attn);

    // Out projection + residual
    mma_gemm<true, false><<<dim3(Ev / 128, Mv / 128), 256, GSMEM>>>(
        attn, out_w, out_b, x, y1, Mv, Ev, Ev);
    ln_kernel<<<Mv, 256>>>(y1, ln1_w, ln1_b, x1);

    // FFN
    mma_gemm<false, true><<<dim3(FFv / 128, Mv / 128), 256, GSMEM>>>(
        x1, fc1_w, fc1_b, nullptr, hb, Mv, FFv, Ev);
    mma_gemm<true, false><<<dim3(Ev / 128, Mv / 128), 256, GSMEM>>>(
        hb, fc2_w, fc2_b, x1, y2, Mv, Ev, FFv);
    ln_kernel<<<Mv, 256>>>(y2, ln2_w, ln2_b, (float*)d_out);

    (void)in_sizes; (void)n_in; (void)out_size;
}

// round 6
// speedup vs baseline: 2.6767x; 1.0309x over previous
#include <cuda_runtime.h>
#include <cuda_bf16.h>
#include <math.h>
#include <stdint.h>

// Problem constants
#define Bv 8
#define Tv 1024
#define Ev 1024
#define Hv 16
#define HDv 64
#define FFv 4096
#define Mv (Bv * Tv)   // 8192 rows

// ---------------------------------------------------------------------------
// Scratch (device globals; no runtime allocation allowed)
// ---------------------------------------------------------------------------
__device__ float g_qkv[(size_t)Mv * 3 * Ev];
__device__ float g_attn[(size_t)Mv * Ev];      // attention out, tf32-rounded
__device__ float g_y1[(size_t)Mv * Ev];
__device__ float g_x1[(size_t)Mv * Ev];        // exact post-LN1 (residual)
__device__ float g_x1r[(size_t)Mv * Ev];       // tf32-rounded post-LN1 (GEMM A)
__device__ float g_h[(size_t)Mv * FFv];        // relu(fc1), tf32-rounded
__device__ float g_y2[(size_t)Mv * Ev];
__device__ float g_xr[(size_t)Mv * Ev];        // tf32-rounded x
__device__ float g_wq[(size_t)3 * Ev * Ev];    // rounded weights
__device__ float g_wo[(size_t)Ev * Ev];
__device__ float g_w1[(size_t)FFv * Ev];
__device__ float g_w2[(size_t)Ev * FFv];
__device__ int   g_len[Bv];

// ---------------------------------------------------------------------------
// Helpers
// ---------------------------------------------------------------------------
__device__ __forceinline__ uint32_t smem_u32(const void* p) {
    uint32_t a;
    asm("{ .reg .u64 t; cvta.to.shared.u64 t, %1; cvt.u32.u64 %0, t; }" : "=r"(a) : "l"(p));
    return a;
}
__device__ __forceinline__ void cp16(uint32_t dst, const void* src) {
    asm volatile("cp.async.cg.shared.global [%0], [%1], 16;" :: "r"(dst), "l"(src));
}
__device__ __forceinline__ float f2tf_f(float f) {
    uint32_t r;
    asm("cvt.rna.tf32.f32 %0, %1;" : "=r"(r) : "f"(f));
    return __uint_as_float(r);
}
__device__ __forceinline__ void mma_tf32(float* c, const uint32_t* a, const uint32_t* b) {
    asm volatile(
        "mma.sync.aligned.m16n8k8.row.col.f32.tf32.tf32.f32 "
        "{%0,%1,%2,%3}, {%4,%5,%6,%7}, {%8,%9}, {%0,%1,%2,%3};"
        : "+f"(c[0]), "+f"(c[1]), "+f"(c[2]), "+f"(c[3])
        : "r"(a[0]), "r"(a[1]), "r"(a[2]), "r"(a[3]), "r"(b[0]), "r"(b[1]));
}

// ---------------------------------------------------------------------------
// tf32 pre-round: out[i] = rna_tf32(in[i]) (vectorized)
// ---------------------------------------------------------------------------
__global__ __launch_bounds__(256) void round_tf32(const float* __restrict__ in,
                                                  float* __restrict__ out, int n4)
{
    int i = blockIdx.x * 256 + threadIdx.x;
    if (i < n4) {
        float4 v = ((const float4*)in)[i];
        v.x = f2tf_f(v.x); v.y = f2tf_f(v.y);
        v.z = f2tf_f(v.z); v.w = f2tf_f(v.w);
        ((float4*)out)[i] = v;
    }
}

// ---------------------------------------------------------------------------
// tf32 mma.sync GEMM:  C = A @ W^T + bias (+Res) (ReLU) (round-out)
// Inputs A, W are PRE-ROUNDED to tf32 — no cvt in the mainloop.
// BM=BN=128, BK=32, 256 threads (2m x 4n warps, 64x32 warp tiles),
// 3-stage cp.async pipeline. smem rows padded to 36 floats.
// ---------------------------------------------------------------------------
#define BKg 32
#define NSTG 3
#define ROWPAD 36
#define TILE_FL (128 * ROWPAD)
#define STAGE_FL (2 * TILE_FL)
#define STAGE_BY (STAGE_FL * 4)                 // 36864 B
#define GSMEM (NSTG * STAGE_BY)                 // 110592 B

__device__ __forceinline__ void load_tiles_g(
    const float* __restrict__ A, const float* __restrict__ W, int K,
    int m0, int n0, int kc, uint32_t sbase, int tid)
{
#pragma unroll
    for (int i = 0; i < 4; i++) {
        int idx = tid + i * 256;
        int r = idx >> 3, q = idx & 7;
        cp16(sbase + r * (ROWPAD * 4) + q * 16,
             A + (size_t)(m0 + r) * K + kc + q * 4);
    }
#pragma unroll
    for (int i = 0; i < 4; i++) {
        int idx = tid + i * 256;
        int r = idx >> 3, q = idx & 7;
        cp16(sbase + TILE_FL * 4 + r * (ROWPAD * 4) + q * 16,
             W + (size_t)(n0 + r) * K + kc + q * 4);
    }
}

template<bool ADD_RES, bool RELU, bool ROUND_OUT>
__global__ __launch_bounds__(256, 2) void mma_gemm(
    const float* __restrict__ A, const float* __restrict__ W,
    const float* __restrict__ bias, const float* __restrict__ Res,
    float* __restrict__ C, int M, int N, int K)
{
    extern __shared__ float smf[];
    const uint32_t sb = smem_u32(smf);
    const int tid = threadIdx.x;
    const int wid = tid >> 5, lid = tid & 31;
    const int wm = wid & 1, wn = wid >> 1;
    const int g = lid >> 2, tg = lid & 3;
    const int m0 = blockIdx.y * 128, n0 = blockIdx.x * 128;

    float acc[4][4][4];
#pragma unroll
    for (int i = 0; i < 4; i++)
#pragma unroll
        for (int j = 0; j < 4; j++)
#pragma unroll
            for (int v = 0; v < 4; v++) acc[i][j][v] = 0.f;

    const int NC = K / BKg;
#pragma unroll
    for (int s = 0; s < NSTG; s++) {
        load_tiles_g(A, W, K, m0, n0, s * BKg, sb + s * STAGE_BY, tid);
        asm volatile("cp.async.commit_group;" ::: "memory");
    }

    for (int c = 0; c < NC; c++) {
        const int s = c % NSTG;
        asm volatile("cp.async.wait_group %0;" :: "n"(NSTG - 1) : "memory");
        __syncthreads();
        const uint32_t* As = (const uint32_t*)(smf + s * STAGE_FL);
        const uint32_t* Ws = As + TILE_FL;

#pragma unroll
        for (int kk = 0; kk < 4; kk++) {
            const int k0 = kk * 8;
            uint32_t af[4][4];
#pragma unroll
            for (int i = 0; i < 4; i++) {
                int rb = wm * 64 + i * 16 + g;
                af[i][0] = As[rb * ROWPAD + k0 + tg];
                af[i][1] = As[(rb + 8) * ROWPAD + k0 + tg];
                af[i][2] = As[rb * ROWPAD + k0 + tg + 4];
                af[i][3] = As[(rb + 8) * ROWPAD + k0 + tg + 4];
            }
            uint32_t bf[4][2];
#pragma unroll
            for (int j = 0; j < 4; j++) {
                int nb = wn * 32 + j * 8 + g;
                bf[j][0] = Ws[nb * ROWPAD + k0 + tg];
                bf[j][1] = Ws[nb * ROWPAD + k0 + tg + 4];
            }
#pragma unroll
            for (int i = 0; i < 4; i++)
#pragma unroll
                for (int j = 0; j < 4; j++)
                    mma_tf32(acc[i][j], af[i], bf[j]);
        }
        __syncthreads();
        if (c + NSTG < NC) {
            load_tiles_g(A, W, K, m0, n0, (c + NSTG) * BKg, sb + s * STAGE_BY, tid);
        }
        asm volatile("cp.async.commit_group;" ::: "memory");
    }

#pragma unroll
    for (int i = 0; i < 4; i++) {
#pragma unroll
        for (int r = 0; r < 2; r++) {
            const size_t row = (size_t)(m0 + wm * 64 + i * 16 + g + r * 8);
#pragma unroll
            for (int j = 0; j < 4; j++) {
                const int col = n0 + wn * 32 + j * 8 + tg * 2;
                float2 o;
                o.x = acc[i][j][r * 2 + 0];
                o.y = acc[i][j][r * 2 + 1];
                const float2 bb = *(const float2*)(bias + col);
                o.x += bb.x; o.y += bb.y;
                if (ADD_RES) {
                    float2 rr = *(const float2*)(Res + row * N + col);
                    o.x += rr.x; o.y += rr.y;
                }
                if (RELU) { o.x = fmaxf(o.x, 0.f); o.y = fmaxf(o.y, 0.f); }
                if (ROUND_OUT) { o.x = f2tf_f(o.x); o.y = f2tf_f(o.y); }
                *(float2*)(C + row * N + col) = o;
            }
        }
    }
}

// ---------------------------------------------------------------------------
// Padding-mask parsing (unchanged)
// ---------------------------------------------------------------------------
__global__ void len_kernel(const unsigned char* __restrict__ raw)
{
    __shared__ int sh_off, sh_f32;
    const int tid = threadIdx.x;
    if (tid == 0) { sh_off = 0; sh_f32 = 0; }
    __syncthreads();
    int f_off = 0, f_f32 = 0;
    for (int i = tid; i < Bv * Tv; i += 256) {
        unsigned char c = raw[i];
        if (c) {
            if ((i & 3) == 3 && c == 0x3f) f_f32 = 1;
            else if ((i & 3) != 0) f_off = 1;
        }
    }
    if (f_off) atomicOr(&sh_off, 1);
    if (f_f32) atomicOr(&sh_f32, 1);
    __syncthreads();
    const bool byte_mode = (sh_f32 == 0) && (sh_off != 0);
    const int w = tid >> 5, lane = tid & 31;
    if (w < Bv) {
        int cnt = 0;
        for (int t = lane; t < Tv; t += 32) {
            int m;
            if (byte_mode) m = (int)raw[w * Tv + t];
            else           m = ((const int*)raw)[w * Tv + t];
            cnt += (m == 0) ? 1 : 0;
        }
#pragma unroll
        for (int off = 16; off > 0; off >>= 1)
            cnt += __shfl_xor_sync(0xffffffffu, cnt, off);
        if (lane == 0) g_len[w] = cnt;
    }
}

// ---------------------------------------------------------------------------
// Fused attention (SIMT flash-style; epilogue rounds output to tf32 since it
// feeds the out-proj GEMM as A)
// ---------------------------------------------------------------------------
#define ATT_SMEM ((2 * 64 * 68 + 64 * 64 + 128) * 4)

__global__ __launch_bounds__(256) void attn_kernel(const float* __restrict__ qkv,
                                                   float* __restrict__ out)
{
    extern __shared__ float sm[];
    float* Qt  = sm;
    float* KtP = sm + 64 * 68;
    float* Vs  = sm + 2 * 64 * 68;
    float* smM = sm + 2 * 64 * 68 + 64 * 64;
    float* smL = smM + 64;

    const int b = blockIdx.z, h = blockIdx.y, qt = blockIdx.x;
    const int tid = threadIdx.x;
    const int tx = tid & 15, ty = tid >> 4;
    const int len = g_len[b];
    const int q0 = qt * 64;
    const long base = (long)b * Tv * (3 * Ev);

#pragma unroll
    for (int u = 0; u < 4; u++) {
        int id = tid + u * 256;
        int r = id >> 4;
        int d4 = (id & 15) << 2;
        float4 v = *(const float4*)(qkv + base + (long)(q0 + r) * (3 * Ev) + h * HDv + d4);
        Qt[(d4 + 0) * 68 + r] = v.x * 0.125f;
        Qt[(d4 + 1) * 68 + r] = v.y * 0.125f;
        Qt[(d4 + 2) * 68 + r] = v.z * 0.125f;
        Qt[(d4 + 3) * 68 + r] = v.w * 0.125f;
    }
    if (tid < 64) { smM[tid] = -1e30f; smL[tid] = 0.f; }

    float o[4][4];
#pragma unroll
    for (int i = 0; i < 4; i++)
#pragma unroll
        for (int j = 0; j < 4; j++) o[i][j] = 0.f;

    const int ktend = min(qt, (len + 63) / 64 - 1);
    for (int kt = 0; kt <= ktend; kt++) {
        __syncthreads();
#pragma unroll
        for (int u = 0; u < 4; u++) {
            int id = tid + u * 256;
            int r = id >> 4;
            int d4 = (id & 15) << 2;
            long rowb = base + (long)(kt * 64 + r) * (3 * Ev) + h * HDv + d4;
            float4 kv = *(const float4*)(qkv + rowb + Ev);
            KtP[(d4 + 0) * 68 + r] = kv.x;
            KtP[(d4 + 1) * 68 + r] = kv.y;
            KtP[(d4 + 2) * 68 + r] = kv.z;
            KtP[(d4 + 3) * 68 + r] = kv.w;
            float4 vv = *(const float4*)(qkv + rowb + 2 * Ev);
            *(float4*)&Vs[r * 64 + d4] = vv;
        }
        __syncthreads();

        float s[4][4];
#pragma unroll
        for (int i = 0; i < 4; i++)
#pragma unroll
            for (int j = 0; j < 4; j++) s[i][j] = 0.f;
#pragma unroll
        for (int d = 0; d < 64; d++) {
            float4 aq = *(const float4*)&Qt[d * 68 + ty * 4];
            float4 bk = *(const float4*)&KtP[d * 68 + tx * 4];
            float av[4] = {aq.x, aq.y, aq.z, aq.w};
            float bv[4] = {bk.x, bk.y, bk.z, bk.w};
#pragma unroll
            for (int i = 0; i < 4; i++)
#pragma unroll
                for (int j = 0; j < 4; j++)
                    s[i][j] = fmaf(av[i], bv[j], s[i][j]);
        }

#pragma unroll
        for (int i = 0; i < 4; i++) {
            int qg = q0 + ty * 4 + i;
#pragma unroll
            for (int j = 0; j < 4; j++) {
                int kg = kt * 64 + tx * 4 + j;
                if (kg > qg || kg >= len) s[i][j] = -1e30f;
            }
        }

        float mnew[4], scl[4], rsum[4], p[4][4];
#pragma unroll
        for (int i = 0; i < 4; i++) {
            float rm = fmaxf(fmaxf(s[i][0], s[i][1]), fmaxf(s[i][2], s[i][3]));
            rm = fmaxf(rm, __shfl_xor_sync(0xffffffffu, rm, 1));
            rm = fmaxf(rm, __shfl_xor_sync(0xffffffffu, rm, 2));
            rm = fmaxf(rm, __shfl_xor_sync(0xffffffffu, rm, 4));
            rm = fmaxf(rm, __shfl_xor_sync(0xffffffffu, rm, 8));
            float mold = smM[ty * 4 + i];
            float mn = fmaxf(mold, rm);
            mnew[i] = mn;
            scl[i] = __expf(mold - mn);
            float rs = 0.f;
#pragma unroll
            for (int j = 0; j < 4; j++) { p[i][j] = __expf(s[i][j] - mn); rs += p[i][j]; }
            rs += __shfl_xor_sync(0xffffffffu, rs, 1);
            rs += __shfl_xor_sync(0xffffffffu, rs, 2);
            rs += __shfl_xor_sync(0xffffffffu, rs, 4);
            rs += __shfl_xor_sync(0xffffffffu, rs, 8);
            rsum[i] = rs;
        }
        if (tx == 0) {
#pragma unroll
            for (int i = 0; i < 4; i++) {
                smM[ty * 4 + i] = mnew[i];
                smL[ty * 4 + i] = smL[ty * 4 + i] * scl[i] + rsum[i];
            }
        }
#pragma unroll
        for (int i = 0; i < 4; i++)
#pragma unroll
            for (int j = 0; j < 4; j++) o[i][j] *= scl[i];

        __syncthreads();
#pragma unroll
        for (int i = 0; i < 4; i++)
            *(float4*)&KtP[(ty * 4 + i) * 68 + tx * 4] =
                make_float4(p[i][0], p[i][1], p[i][2], p[i][3]);
        __syncthreads();

#pragma unroll
        for (int k = 0; k < 64; k++) {
            float a0 = KtP[(ty * 4 + 0) * 68 + k];
            float a1 = KtP[(ty * 4 + 1) * 68 + k];
            float a2 = KtP[(ty * 4 + 2) * 68 + k];
            float a3 = KtP[(ty * 4 + 3) * 68 + k];
            float4 bv = *(const float4*)&Vs[k * 64 + tx * 4];
            o[0][0] = fmaf(a0, bv.x, o[0][0]); o[0][1] = fmaf(a0, bv.y, o[0][1]);
            o[0][2] = fmaf(a0, bv.z, o[0][2]); o[0][3] = fmaf(a0, bv.w, o[0][3]);
            o[1][0] = fmaf(a1, bv.x, o[1][0]); o[1][1] = fmaf(a1, bv.y, o[1][1]);
            o[1][2] = fmaf(a1, bv.z, o[1][2]); o[1][3] = fmaf(a1, bv.w, o[1][3]);
            o[2][0] = fmaf(a2, bv.x, o[2][0]); o[2][1] = fmaf(a2, bv.y, o[2][1]);
            o[2][2] = fmaf(a2, bv.z, o[2][2]); o[2][3] = fmaf(a2, bv.w, o[2][3]);
            o[3][0] = fmaf(a3, bv.x, o[3][0]); o[3][1] = fmaf(a3, bv.y, o[3][1]);
            o[3][2] = fmaf(a3, bv.z, o[3][2]); o[3][3] = fmaf(a3, bv.w, o[3][3]);
        }
    }
    __syncthreads();

#pragma unroll
    for (int i = 0; i < 4; i++) {
        float inv = 1.f / smL[ty * 4 + i];
        long row = (long)b * Tv + q0 + ty * 4 + i;
        float4 r = make_float4(f2tf_f(o[i][0] * inv), f2tf_f(o[i][1] * inv),
                               f2tf_f(o[i][2] * inv), f2tf_f(o[i][3] * inv));
        *(float4*)(out + row * Ev + h * HDv + tx * 4) = r;
    }
}

// ---------------------------------------------------------------------------
// LayerNorm; optionally emits a second tf32-rounded copy (GEMM A input)
// ---------------------------------------------------------------------------
template<bool DUAL>
__global__ __launch_bounds__(256) void ln_kernel(const float* __restrict__ X,
                                                 const float* __restrict__ w,
                                                 const float* __restrict__ bvec,
                                                 float* __restrict__ out,
                                                 float* __restrict__ out_r)
{
    const int row = blockIdx.x;
    const int tid = threadIdx.x;
    const float4 v = *(const float4*)(X + (long)row * Ev + tid * 4);
    float s = v.x + v.y + v.z + v.w;
    float q = v.x * v.x + v.y * v.y + v.z * v.z + v.w * v.w;
#pragma unroll
    for (int off = 16; off > 0; off >>= 1) {
        s += __shfl_xor_sync(0xffffffffu, s, off);
        q += __shfl_xor_sync(0xffffffffu, q, off);
    }
    __shared__ float red[16];
    __shared__ float sh_u, sh_r;
    const int wid = tid >> 5, lane = tid & 31;
    if (lane == 0) { red[wid] = s; red[8 + wid] = q; }
    __syncthreads();
    if (tid == 0) {
        float S = 0.f, Q = 0.f;
#pragma unroll
        for (int i = 0; i < 8; i++) { S += red[i]; Q += red[8 + i]; }
        float u = S * (1.f / 1024.f);
        float var = fmaxf(Q * (1.f / 1024.f) - u * u, 0.f);
        sh_u = u;
        sh_r = rsqrtf(var + 1e-12f);
    }
    __syncthreads();
    const float u = sh_u, rstd = sh_r;
    float4 ww = *(const float4*)(w + tid * 4);
    float4 bb = *(const float4*)(bvec + tid * 4);
    float4 o;
    o.x = (v.x - u) * rstd * ww.x + bb.x;
    o.y = (v.y - u) * rstd * ww.y + bb.y;
    o.z = (v.z - u) * rstd * ww.z + bb.z;
    o.w = (v.w - u) * rstd * ww.w + bb.w;
    *(float4*)(out + (long)row * Ev + tid * 4) = o;
    if (DUAL) {
        float4 r = make_float4(f2tf_f(o.x), f2tf_f(o.y), f2tf_f(o.z), f2tf_f(o.w));
        *(float4*)(out_r + (long)row * Ev + tid * 4) = r;
    }
}

// ---------------------------------------------------------------------------
// Launch
// ---------------------------------------------------------------------------
extern "C" void kernel_launch(void* const* d_in, const int* in_sizes, int n_in,
                              void* d_out, int out_size)
{
    const float* x     = (const float*)d_in[0];
    const float* in_w  = (const float*)d_in[1];
    const float* in_b  = (const float*)d_in[2];
    const float* out_w = (const float*)d_in[3];
    const float* out_b = (const float*)d_in[4];
    const float* fc1_w = (const float*)d_in[5];
    const float* fc1_b = (const float*)d_in[6];
    const float* fc2_w = (const float*)d_in[7];
    const float* fc2_b = (const float*)d_in[8];
    const float* ln1_w = (const float*)d_in[9];
    const float* ln1_b = (const float*)d_in[10];
    const float* ln2_w = (const float*)d_in[11];
    const float* ln2_b = (const float*)d_in[12];

    const unsigned char* pmask = (const unsigned char*)d_in[13];
    for (int i = 0; i < n_in; i++)
        if (in_sizes[i] == Bv * Tv) { pmask = (const unsigned char*)d_in[i]; break; }

    float *qkv, *attn, *y1, *x1, *x1r, *hb, *y2, *xr, *wq, *wo, *w1, *w2;
    cudaGetSymbolAddress((void**)&qkv,  g_qkv);
    cudaGetSymbolAddress((void**)&attn, g_attn);
    cudaGetSymbolAddress((void**)&y1,   g_y1);
    cudaGetSymbolAddress((void**)&x1,   g_x1);
    cudaGetSymbolAddress((void**)&x1r,  g_x1r);
    cudaGetSymbolAddress((void**)&hb,   g_h);
    cudaGetSymbolAddress((void**)&y2,   g_y2);
    cudaGetSymbolAddress((void**)&xr,   g_xr);
    cudaGetSymbolAddress((void**)&wq,   g_wq);
    cudaGetSymbolAddress((void**)&wo,   g_wo);
    cudaGetSymbolAddress((void**)&w1,   g_w1);
    cudaGetSymbolAddress((void**)&w2,   g_w2);

    cudaFuncSetAttribute(attn_kernel, cudaFuncAttributeMaxDynamicSharedMemorySize, ATT_SMEM);
    cudaFuncSetAttribute(mma_gemm<false, false, false>, cudaFuncAttributeMaxDynamicSharedMemorySize, GSMEM);
    cudaFuncSetAttribute(mma_gemm<true,  false, false>, cudaFuncAttributeMaxDynamicSharedMemorySize, GSMEM);
    cudaFuncSetAttribute(mma_gemm<false, true,  true >, cudaFuncAttributeMaxDynamicSharedMemorySize, GSMEM);

    len_kernel<<<1, 256>>>(pmask);

    // tf32 pre-rounding (exact rna, once per element)
    round_tf32<<<(Mv * Ev / 4 + 255) / 256, 256>>>(x, xr, Mv * Ev / 4);
    round_tf32<<<(3 * Ev * Ev / 4 + 255) / 256, 256>>>(in_w, wq, 3 * Ev * Ev / 4);
    round_tf32<<<(Ev * Ev / 4 + 255) / 256, 256>>>(out_w, wo, Ev * Ev / 4);
    round_tf32<<<(FFv * Ev / 4 + 255) / 256, 256>>>(fc1_w, w1, FFv * Ev / 4);
    round_tf32<<<(Ev * FFv / 4 + 255) / 256, 256>>>(fc2_w, w2, Ev * FFv / 4);

    // QKV projection
    mma_gemm<false, false, false><<<dim3(3 * Ev / 128, Mv / 128), 256, GSMEM>>>(
        xr, wq, in_b, nullptr, qkv, Mv, 3 * Ev, Ev);

    // Fused causal attention (+ key padding); output tf32-rounded
    attn_kernel<<<dim3(Tv / 64, Hv, Bv), 256, ATT_SMEM>>>(qkv, attn);

    // Out projection + residual (residual = exact x)
    mma_gemm<true, false, false><<<dim3(Ev / 128, Mv / 128), 256, GSMEM>>>(
        attn, wo, out_b, x, y1, Mv, Ev, Ev);
    ln_kernel<true><<<Mv, 256>>>(y1, ln1_w, ln1_b, x1, x1r);

    // FFN
    mma_gemm<false, true, true><<<dim3(FFv / 128, Mv / 128), 256, GSMEM>>>(
        x1r, w1, fc1_b, nullptr, hb, Mv, FFv, Ev);
    mma_gemm<true, false, false><<<dim3(Ev / 128, Mv / 128), 256, GSMEM>>>(
        hb, w2, fc2_b, x1, y2, Mv, Ev, FFv);
    ln_kernel<false><<<Mv, 256>>>(y2, ln2_w, ln2_b, (float*)d_out, nullptr);

    (void)in_sizes; (void)n_in; (void)out_size;
}

// round 7
// speedup vs baseline: 2.8059x; 1.0483x over previous
#include <cuda_runtime.h>
#include <cuda_bf16.h>
#include <math.h>
#include <stdint.h>

// Problem constants
#define Bv 8
#define Tv 1024
#define Ev 1024
#define Hv 16
#define HDv 64
#define FFv 4096
#define Mv (Bv * Tv)   // 8192 rows

// ---------------------------------------------------------------------------
// Scratch (device globals; no runtime allocation allowed)
// ---------------------------------------------------------------------------
__device__ float g_qkv[(size_t)Mv * 3 * Ev];
__device__ float g_attn[(size_t)Mv * Ev];      // attention out, tf32-rounded
__device__ float g_y1[(size_t)Mv * Ev];
__device__ float g_x1[(size_t)Mv * Ev];        // exact post-LN1 (residual)
__device__ float g_x1r[(size_t)Mv * Ev];       // tf32-rounded post-LN1 (GEMM A)
__device__ float g_h[(size_t)Mv * FFv];        // relu(fc1), tf32-rounded
__device__ float g_y2[(size_t)Mv * Ev];
__device__ float g_xr[(size_t)Mv * Ev];        // tf32-rounded x
__device__ float g_wq[(size_t)3 * Ev * Ev];    // rounded weights
__device__ float g_wo[(size_t)Ev * Ev];
__device__ float g_w1[(size_t)FFv * Ev];
__device__ float g_w2[(size_t)Ev * FFv];
__device__ int   g_len[Bv];

// ---------------------------------------------------------------------------
// Helpers
// ---------------------------------------------------------------------------
__device__ __forceinline__ uint32_t smem_u32(const void* p) {
    uint32_t a;
    asm("{ .reg .u64 t; cvta.to.shared.u64 t, %1; cvt.u32.u64 %0, t; }" : "=r"(a) : "l"(p));
    return a;
}
__device__ __forceinline__ void cp16(uint32_t dst, const void* src) {
    asm volatile("cp.async.cg.shared.global [%0], [%1], 16;" :: "r"(dst), "l"(src));
}
__device__ __forceinline__ float f2tf_f(float f) {
    uint32_t r;
    asm("cvt.rna.tf32.f32 %0, %1;" : "=r"(r) : "f"(f));
    return __uint_as_float(r);
}
__device__ __forceinline__ void mma_tf32(float* c, const uint32_t* a, const uint32_t* b) {
    asm volatile(
        "mma.sync.aligned.m16n8k8.row.col.f32.tf32.tf32.f32 "
        "{%0,%1,%2,%3}, {%4,%5,%6,%7}, {%8,%9}, {%0,%1,%2,%3};"
        : "+f"(c[0]), "+f"(c[1]), "+f"(c[2]), "+f"(c[3])
        : "r"(a[0]), "r"(a[1]), "r"(a[2]), "r"(a[3]), "r"(b[0]), "r"(b[1]));
}

// ---------------------------------------------------------------------------
// tf32 pre-round: out[i] = rna_tf32(in[i]) (vectorized)
// ---------------------------------------------------------------------------
__global__ __launch_bounds__(256) void round_tf32(const float* __restrict__ in,
                                                  float* __restrict__ out, int n4)
{
    int i = blockIdx.x * 256 + threadIdx.x;
    if (i < n4) {
        float4 v = ((const float4*)in)[i];
        v.x = f2tf_f(v.x); v.y = f2tf_f(v.y);
        v.z = f2tf_f(v.z); v.w = f2tf_f(v.w);
        ((float4*)out)[i] = v;
    }
}

// ---------------------------------------------------------------------------
// tf32 mma.sync GEMM:  C = A @ W^T + bias (+Res) (ReLU) (round-out)
// Inputs A, W PRE-ROUNDED to tf32.
// BM=BN=128, BK=32, 128 threads (2x2 warps, 64x64 warp tiles — doubles
// fragment reuse, halves smem bytes/MAC), 3-stage cp.async, 2 CTAs/SM.
// ---------------------------------------------------------------------------
#define BKg 32
#define NSTG 3
#define ROWPAD 36
#define TILE_FL (128 * ROWPAD)
#define STAGE_FL (2 * TILE_FL)
#define STAGE_BY (STAGE_FL * 4)                 // 36864 B
#define GSMEM (NSTG * STAGE_BY)                 // 110592 B

__device__ __forceinline__ void load_tiles_g(
    const float* __restrict__ A, const float* __restrict__ W, int K,
    int m0, int n0, int kc, uint32_t sbase, int tid)
{
#pragma unroll
    for (int i = 0; i < 8; i++) {               // A tile: 128 rows x 8 float4
        int idx = tid + i * 128;
        int r = idx >> 3, q = idx & 7;
        cp16(sbase + r * (ROWPAD * 4) + q * 16,
             A + (size_t)(m0 + r) * K + kc + q * 4);
    }
#pragma unroll
    for (int i = 0; i < 8; i++) {               // W tile
        int idx = tid + i * 128;
        int r = idx >> 3, q = idx & 7;
        cp16(sbase + TILE_FL * 4 + r * (ROWPAD * 4) + q * 16,
             W + (size_t)(n0 + r) * K + kc + q * 4);
    }
}

template<bool ADD_RES, bool RELU, bool ROUND_OUT>
__global__ __launch_bounds__(128, 2) void mma_gemm(
    const float* __restrict__ A, const float* __restrict__ W,
    const float* __restrict__ bias, const float* __restrict__ Res,
    float* __restrict__ C, int M, int N, int K)
{
    extern __shared__ float smf[];
    const uint32_t sb = smem_u32(smf);
    const int tid = threadIdx.x;
    const int wid = tid >> 5, lid = tid & 31;
    const int wm = wid & 1, wn = wid >> 1;      // 2 x 2 warp grid
    const int g = lid >> 2, tg = lid & 3;
    const int m0 = blockIdx.y * 128, n0 = blockIdx.x * 128;

    float acc[4][8][4];
#pragma unroll
    for (int i = 0; i < 4; i++)
#pragma unroll
        for (int j = 0; j < 8; j++)
#pragma unroll
            for (int v = 0; v < 4; v++) acc[i][j][v] = 0.f;

    const int NC = K / BKg;
#pragma unroll
    for (int s = 0; s < NSTG; s++) {
        load_tiles_g(A, W, K, m0, n0, s * BKg, sb + s * STAGE_BY, tid);
        asm volatile("cp.async.commit_group;" ::: "memory");
    }

    for (int c = 0; c < NC; c++) {
        const int s = c % NSTG;
        asm volatile("cp.async.wait_group %0;" :: "n"(NSTG - 1) : "memory");
        __syncthreads();
        const uint32_t* As = (const uint32_t*)(smf + s * STAGE_FL);
        const uint32_t* Ws = As + TILE_FL;

#pragma unroll
        for (int kk = 0; kk < 4; kk++) {
            const int k0 = kk * 8;
            uint32_t af[4][4];
#pragma unroll
            for (int i = 0; i < 4; i++) {
                int rb = wm * 64 + i * 16 + g;
                af[i][0] = As[rb * ROWPAD + k0 + tg];
                af[i][1] = As[(rb + 8) * ROWPAD + k0 + tg];
                af[i][2] = As[rb * ROWPAD + k0 + tg + 4];
                af[i][3] = As[(rb + 8) * ROWPAD + k0 + tg + 4];
            }
            uint32_t bf[8][2];
#pragma unroll
            for (int j = 0; j < 8; j++) {
                int nb = wn * 64 + j * 8 + g;
                bf[j][0] = Ws[nb * ROWPAD + k0 + tg];
                bf[j][1] = Ws[nb * ROWPAD + k0 + tg + 4];
            }
#pragma unroll
            for (int i = 0; i < 4; i++)
#pragma unroll
                for (int j = 0; j < 8; j++)
                    mma_tf32(acc[i][j], af[i], bf[j]);
        }
        __syncthreads();
        if (c + NSTG < NC) {
            load_tiles_g(A, W, K, m0, n0, (c + NSTG) * BKg, sb + s * STAGE_BY, tid);
        }
        asm volatile("cp.async.commit_group;" ::: "memory");
    }

#pragma unroll
    for (int i = 0; i < 4; i++) {
#pragma unroll
        for (int r = 0; r < 2; r++) {
            const size_t row = (size_t)(m0 + wm * 64 + i * 16 + g + r * 8);
#pragma unroll
            for (int j = 0; j < 8; j++) {
                const int col = n0 + wn * 64 + j * 8 + tg * 2;
                float2 o;
                o.x = acc[i][j][r * 2 + 0];
                o.y = acc[i][j][r * 2 + 1];
                const float2 bb = *(const float2*)(bias + col);
                o.x += bb.x; o.y += bb.y;
                if (ADD_RES) {
                    float2 rr = *(const float2*)(Res + row * N + col);
                    o.x += rr.x; o.y += rr.y;
                }
                if (RELU) { o.x = fmaxf(o.x, 0.f); o.y = fmaxf(o.y, 0.f); }
                if (ROUND_OUT) { o.x = f2tf_f(o.x); o.y = f2tf_f(o.y); }
                *(float2*)(C + row * N + col) = o;
            }
        }
    }
}

// ---------------------------------------------------------------------------
// Padding-mask parsing (unchanged)
// ---------------------------------------------------------------------------
__global__ void len_kernel(const unsigned char* __restrict__ raw)
{
    __shared__ int sh_off, sh_f32;
    const int tid = threadIdx.x;
    if (tid == 0) { sh_off = 0; sh_f32 = 0; }
    __syncthreads();
    int f_off = 0, f_f32 = 0;
    for (int i = tid; i < Bv * Tv; i += 256) {
        unsigned char c = raw[i];
        if (c) {
            if ((i & 3) == 3 && c == 0x3f) f_f32 = 1;
            else if ((i & 3) != 0) f_off = 1;
        }
    }
    if (f_off) atomicOr(&sh_off, 1);
    if (f_f32) atomicOr(&sh_f32, 1);
    __syncthreads();
    const bool byte_mode = (sh_f32 == 0) && (sh_off != 0);
    const int w = tid >> 5, lane = tid & 31;
    if (w < Bv) {
        int cnt = 0;
        for (int t = lane; t < Tv; t += 32) {
            int m;
            if (byte_mode) m = (int)raw[w * Tv + t];
            else           m = ((const int*)raw)[w * Tv + t];
            cnt += (m == 0) ? 1 : 0;
        }
#pragma unroll
        for (int off = 16; off > 0; off >>= 1)
            cnt += __shfl_xor_sync(0xffffffffu, cnt, off);
        if (lane == 0) g_len[w] = cnt;
    }
}

// ---------------------------------------------------------------------------
// Fused attention (SIMT flash-style; epilogue rounds output to tf32)
// ---------------------------------------------------------------------------
#define ATT_SMEM ((2 * 64 * 68 + 64 * 64 + 128) * 4)

__global__ __launch_bounds__(256) void attn_kernel(const float* __restrict__ qkv,
                                                   float* __restrict__ out)
{
    extern __shared__ float sm[];
    float* Qt  = sm;
    float* KtP = sm + 64 * 68;
    float* Vs  = sm + 2 * 64 * 68;
    float* smM = sm + 2 * 64 * 68 + 64 * 64;
    float* smL = smM + 64;

    const int b = blockIdx.z, h = blockIdx.y, qt = blockIdx.x;
    const int tid = threadIdx.x;
    const int tx = tid & 15, ty = tid >> 4;
    const int len = g_len[b];
    const int q0 = qt * 64;
    const long base = (long)b * Tv * (3 * Ev);

#pragma unroll
    for (int u = 0; u < 4; u++) {
        int id = tid + u * 256;
        int r = id >> 4;
        int d4 = (id & 15) << 2;
        float4 v = *(const float4*)(qkv + base + (long)(q0 + r) * (3 * Ev) + h * HDv + d4);
        Qt[(d4 + 0) * 68 + r] = v.x * 0.125f;
        Qt[(d4 + 1) * 68 + r] = v.y * 0.125f;
        Qt[(d4 + 2) * 68 + r] = v.z * 0.125f;
        Qt[(d4 + 3) * 68 + r] = v.w * 0.125f;
    }
    if (tid < 64) { smM[tid] = -1e30f; smL[tid] = 0.f; }

    float o[4][4];
#pragma unroll
    for (int i = 0; i < 4; i++)
#pragma unroll
        for (int j = 0; j < 4; j++) o[i][j] = 0.f;

    const int ktend = min(qt, (len + 63) / 64 - 1);
    for (int kt = 0; kt <= ktend; kt++) {
        __syncthreads();
#pragma unroll
        for (int u = 0; u < 4; u++) {
            int id = tid + u * 256;
            int r = id >> 4;
            int d4 = (id & 15) << 2;
            long rowb = base + (long)(kt * 64 + r) * (3 * Ev) + h * HDv + d4;
            float4 kv = *(const float4*)(qkv + rowb + Ev);
            KtP[(d4 + 0) * 68 + r] = kv.x;
            KtP[(d4 + 1) * 68 + r] = kv.y;
            KtP[(d4 + 2) * 68 + r] = kv.z;
            KtP[(d4 + 3) * 68 + r] = kv.w;
            float4 vv = *(const float4*)(qkv + rowb + 2 * Ev);
            *(float4*)&Vs[r * 64 + d4] = vv;
        }
        __syncthreads();

        float s[4][4];
#pragma unroll
        for (int i = 0; i < 4; i++)
#pragma unroll
            for (int j = 0; j < 4; j++) s[i][j] = 0.f;
#pragma unroll
        for (int d = 0; d < 64; d++) {
            float4 aq = *(const float4*)&Qt[d * 68 + ty * 4];
            float4 bk = *(const float4*)&KtP[d * 68 + tx * 4];
            float av[4] = {aq.x, aq.y, aq.z, aq.w};
            float bv[4] = {bk.x, bk.y, bk.z, bk.w};
#pragma unroll
            for (int i = 0; i < 4; i++)
#pragma unroll
                for (int j = 0; j < 4; j++)
                    s[i][j] = fmaf(av[i], bv[j], s[i][j]);
        }

#pragma unroll
        for (int i = 0; i < 4; i++) {
            int qg = q0 + ty * 4 + i;
#pragma unroll
            for (int j = 0; j < 4; j++) {
                int kg = kt * 64 + tx * 4 + j;
                if (kg > qg || kg >= len) s[i][j] = -1e30f;
            }
        }

        float mnew[4], scl[4], rsum[4], p[4][4];
#pragma unroll
        for (int i = 0; i < 4; i++) {
            float rm = fmaxf(fmaxf(s[i][0], s[i][1]), fmaxf(s[i][2], s[i][3]));
            rm = fmaxf(rm, __shfl_xor_sync(0xffffffffu, rm, 1));
            rm = fmaxf(rm, __shfl_xor_sync(0xffffffffu, rm, 2));
            rm = fmaxf(rm, __shfl_xor_sync(0xffffffffu, rm, 4));
            rm = fmaxf(rm, __shfl_xor_sync(0xffffffffu, rm, 8));
            float mold = smM[ty * 4 + i];
            float mn = fmaxf(mold, rm);
            mnew[i] = mn;
            scl[i] = __expf(mold - mn);
            float rs = 0.f;
#pragma unroll
            for (int j = 0; j < 4; j++) { p[i][j] = __expf(s[i][j] - mn); rs += p[i][j]; }
            rs += __shfl_xor_sync(0xffffffffu, rs, 1);
            rs += __shfl_xor_sync(0xffffffffu, rs, 2);
            rs += __shfl_xor_sync(0xffffffffu, rs, 4);
            rs += __shfl_xor_sync(0xffffffffu, rs, 8);
            rsum[i] = rs;
        }
        if (tx == 0) {
#pragma unroll
            for (int i = 0; i < 4; i++) {
                smM[ty * 4 + i] = mnew[i];
                smL[ty * 4 + i] = smL[ty * 4 + i] * scl[i] + rsum[i];
            }
        }
#pragma unroll
        for (int i = 0; i < 4; i++)
#pragma unroll
            for (int j = 0; j < 4; j++) o[i][j] *= scl[i];

        __syncthreads();
#pragma unroll
        for (int i = 0; i < 4; i++)
            *(float4*)&KtP[(ty * 4 + i) * 68 + tx * 4] =
                make_float4(p[i][0], p[i][1], p[i][2], p[i][3]);
        __syncthreads();

#pragma unroll
        for (int k = 0; k < 64; k++) {
            float a0 = KtP[(ty * 4 + 0) * 68 + k];
            float a1 = KtP[(ty * 4 + 1) * 68 + k];
            float a2 = KtP[(ty * 4 + 2) * 68 + k];
            float a3 = KtP[(ty * 4 + 3) * 68 + k];
            float4 bv = *(const float4*)&Vs[k * 64 + tx * 4];
            o[0][0] = fmaf(a0, bv.x, o[0][0]); o[0][1] = fmaf(a0, bv.y, o[0][1]);
            o[0][2] = fmaf(a0, bv.z, o[0][2]); o[0][3] = fmaf(a0, bv.w, o[0][3]);
            o[1][0] = fmaf(a1, bv.x, o[1][0]); o[1][1] = fmaf(a1, bv.y, o[1][1]);
            o[1][2] = fmaf(a1, bv.z, o[1][2]); o[1][3] = fmaf(a1, bv.w, o[1][3]);
            o[2][0] = fmaf(a2, bv.x, o[2][0]); o[2][1] = fmaf(a2, bv.y, o[2][1]);
            o[2][2] = fmaf(a2, bv.z, o[2][2]); o[2][3] = fmaf(a2, bv.w, o[2][3]);
            o[3][0] = fmaf(a3, bv.x, o[3][0]); o[3][1] = fmaf(a3, bv.y, o[3][1]);
            o[3][2] = fmaf(a3, bv.z, o[3][2]); o[3][3] = fmaf(a3, bv.w, o[3][3]);
        }
    }
    __syncthreads();

#pragma unroll
    for (int i = 0; i < 4; i++) {
        float inv = 1.f / smL[ty * 4 + i];
        long row = (long)b * Tv + q0 + ty * 4 + i;
        float4 r = make_float4(f2tf_f(o[i][0] * inv), f2tf_f(o[i][1] * inv),
                               f2tf_f(o[i][2] * inv), f2tf_f(o[i][3] * inv));
        *(float4*)(out + row * Ev + h * HDv + tx * 4) = r;
    }
}

// ---------------------------------------------------------------------------
// LayerNorm; optionally emits a second tf32-rounded copy (GEMM A input)
// ---------------------------------------------------------------------------
template<bool DUAL>
__global__ __launch_bounds__(256) void ln_kernel(const float* __restrict__ X,
                                                 const float* __restrict__ w,
                                                 const float* __restrict__ bvec,
                                                 float* __restrict__ out,
                                                 float* __restrict__ out_r)
{
    const int row = blockIdx.x;
    const int tid = threadIdx.x;
    const float4 v = *(const float4*)(X + (long)row * Ev + tid * 4);
    float s = v.x + v.y + v.z + v.w;
    float q = v.x * v.x + v.y * v.y + v.z * v.z + v.w * v.w;
#pragma unroll
    for (int off = 16; off > 0; off >>= 1) {
        s += __shfl_xor_sync(0xffffffffu, s, off);
        q += __shfl_xor_sync(0xffffffffu, q, off);
    }
    __shared__ float red[16];
    __shared__ float sh_u, sh_r;
    const int wid = tid >> 5, lane = tid & 31;
    if (lane == 0) { red[wid] = s; red[8 + wid] = q; }
    __syncthreads();
    if (tid == 0) {
        float S = 0.f, Q = 0.f;
#pragma unroll
        for (int i = 0; i < 8; i++) { S += red[i]; Q += red[8 + i]; }
        float u = S * (1.f / 1024.f);
        float var = fmaxf(Q * (1.f / 1024.f) - u * u, 0.f);
        sh_u = u;
        sh_r = rsqrtf(var + 1e-12f);
    }
    __syncthreads();
    const float u = sh_u, rstd = sh_r;
    float4 ww = *(const float4*)(w + tid * 4);
    float4 bb = *(const float4*)(bvec + tid * 4);
    float4 o;
    o.x = (v.x - u) * rstd * ww.x + bb.x;
    o.y = (v.y - u) * rstd * ww.y + bb.y;
    o.z = (v.z - u) * rstd * ww.z + bb.z;
    o.w = (v.w - u) * rstd * ww.w + bb.w;
    *(float4*)(out + (long)row * Ev + tid * 4) = o;
    if (DUAL) {
        float4 r = make_float4(f2tf_f(o.x), f2tf_f(o.y), f2tf_f(o.z), f2tf_f(o.w));
        *(float4*)(out_r + (long)row * Ev + tid * 4) = r;
    }
}

// ---------------------------------------------------------------------------
// Launch
// ---------------------------------------------------------------------------
extern "C" void kernel_launch(void* const* d_in, const int* in_sizes, int n_in,
                              void* d_out, int out_size)
{
    const float* x     = (const float*)d_in[0];
    const float* in_w  = (const float*)d_in[1];
    const float* in_b  = (const float*)d_in[2];
    const float* out_w = (const float*)d_in[3];
    const float* out_b = (const float*)d_in[4];
    const float* fc1_w = (const float*)d_in[5];
    const float* fc1_b = (const float*)d_in[6];
    const float* fc2_w = (const float*)d_in[7];
    const float* fc2_b = (const float*)d_in[8];
    const float* ln1_w = (const float*)d_in[9];
    const float* ln1_b = (const float*)d_in[10];
    const float* ln2_w = (const float*)d_in[11];
    const float* ln2_b = (const float*)d_in[12];

    const unsigned char* pmask = (const unsigned char*)d_in[13];
    for (int i = 0; i < n_in; i++)
        if (in_sizes[i] == Bv * Tv) { pmask = (const unsigned char*)d_in[i]; break; }

    float *qkv, *attn, *y1, *x1, *x1r, *hb, *y2, *xr, *wq, *wo, *w1, *w2;
    cudaGetSymbolAddress((void**)&qkv,  g_qkv);
    cudaGetSymbolAddress((void**)&attn, g_attn);
    cudaGetSymbolAddress((void**)&y1,   g_y1);
    cudaGetSymbolAddress((void**)&x1,   g_x1);
    cudaGetSymbolAddress((void**)&x1r,  g_x1r);
    cudaGetSymbolAddress((void**)&hb,   g_h);
    cudaGetSymbolAddress((void**)&y2,   g_y2);
    cudaGetSymbolAddress((void**)&xr,   g_xr);
    cudaGetSymbolAddress((void**)&wq,   g_wq);
    cudaGetSymbolAddress((void**)&wo,   g_wo);
    cudaGetSymbolAddress((void**)&w1,   g_w1);
    cudaGetSymbolAddress((void**)&w2,   g_w2);

    cudaFuncSetAttribute(attn_kernel, cudaFuncAttributeMaxDynamicSharedMemorySize, ATT_SMEM);
    cudaFuncSetAttribute(mma_gemm<false, false, false>, cudaFuncAttributeMaxDynamicSharedMemorySize, GSMEM);
    cudaFuncSetAttribute(mma_gemm<true,  false, false>, cudaFuncAttributeMaxDynamicSharedMemorySize, GSMEM);
    cudaFuncSetAttribute(mma_gemm<false, true,  true >, cudaFuncAttributeMaxDynamicSharedMemorySize, GSMEM);

    len_kernel<<<1, 256>>>(pmask);

    // tf32 pre-rounding (exact rna, once per element)
    round_tf32<<<(Mv * Ev / 4 + 255) / 256, 256>>>(x, xr, Mv * Ev / 4);
    round_tf32<<<(3 * Ev * Ev / 4 + 255) / 256, 256>>>(in_w, wq, 3 * Ev * Ev / 4);
    round_tf32<<<(Ev * Ev / 4 + 255) / 256, 256>>>(out_w, wo, Ev * Ev / 4);
    round_tf32<<<(FFv * Ev / 4 + 255) / 256, 256>>>(fc1_w, w1, FFv * Ev / 4);
    round_tf32<<<(Ev * FFv / 4 + 255) / 256, 256>>>(fc2_w, w2, Ev * FFv / 4);

    // QKV projection
    mma_gemm<false, false, false><<<dim3(3 * Ev / 128, Mv / 128), 128, GSMEM>>>(
        xr, wq, in_b, nullptr, qkv, Mv, 3 * Ev, Ev);

    // Fused causal attention (+ key padding); output tf32-rounded
    attn_kernel<<<dim3(Tv / 64, Hv, Bv), 256, ATT_SMEM>>>(qkv, attn);

    // Out projection + residual (residual = exact x)
    mma_gemm<true, false, false><<<dim3(Ev / 128, Mv / 128), 128, GSMEM>>>(
        attn, wo, out_b, x, y1, Mv, Ev, Ev);
    ln_kernel<true><<<Mv, 256>>>(y1, ln1_w, ln1_b, x1, x1r);

    // FFN
    mma_gemm<false, true, true><<<dim3(FFv / 128, Mv / 128), 128, GSMEM>>>(
        x1r, w1, fc1_b, nullptr, hb, Mv, FFv, Ev);
    mma_gemm<true, false, false><<<dim3(Ev / 128, Mv / 128), 128, GSMEM>>>(
        hb, w2, fc2_b, x1, y2, Mv, Ev, FFv);
    ln_kernel<false><<<Mv, 256>>>(y2, ln2_w, ln2_b, (float*)d_out, nullptr);

    (void)in_sizes; (void)n_in; (void)out_size;
}

// round 9
// speedup vs baseline: 3.4812x; 1.2407x over previous
#include <cuda_runtime.h>
#include <cuda_bf16.h>
#include <math.h>
#include <stdint.h>

// Problem constants
#define Bv 8
#define Tv 1024
#define Ev 1024
#define Hv 16
#define HDv 64
#define FFv 4096
#define Mv (Bv * Tv)   // 8192 rows

// ---------------------------------------------------------------------------
// Scratch (device globals; no runtime allocation allowed)
// ---------------------------------------------------------------------------
__device__ float g_qkv[(size_t)Mv * 3 * Ev];   // tf32-rounded qkv
__device__ float g_attn[(size_t)Mv * Ev];      // attention out, tf32-rounded
__device__ float g_y1[(size_t)Mv * Ev];
__device__ float g_x1[(size_t)Mv * Ev];        // exact post-LN1 (residual)
__device__ float g_x1r[(size_t)Mv * Ev];       // tf32-rounded post-LN1 (GEMM A)
__device__ float g_h[(size_t)Mv * FFv];        // relu(fc1), tf32-rounded
__device__ float g_y2[(size_t)Mv * Ev];
__device__ float g_xr[(size_t)Mv * Ev];        // tf32-rounded x
__device__ float g_wq[(size_t)3 * Ev * Ev];    // rounded weights
__device__ float g_wo[(size_t)Ev * Ev];
__device__ float g_w1[(size_t)FFv * Ev];
__device__ float g_w2[(size_t)Ev * FFv];
__device__ int   g_len[Bv];

// ---------------------------------------------------------------------------
// Helpers
// ---------------------------------------------------------------------------
__device__ __forceinline__ uint32_t smem_u32(const void* p) {
    uint32_t a;
    asm("{ .reg .u64 t; cvta.to.shared.u64 t, %1; cvt.u32.u64 %0, t; }" : "=r"(a) : "l"(p));
    return a;
}
__device__ __forceinline__ void cp16(uint32_t dst, const void* src) {
    asm volatile("cp.async.cg.shared.global [%0], [%1], 16;" :: "r"(dst), "l"(src));
}
__device__ __forceinline__ float f2tf_f(float f) {
    uint32_t r;
    asm("cvt.rna.tf32.f32 %0, %1;" : "=r"(r) : "f"(f));
    return __uint_as_float(r);
}
__device__ __forceinline__ void mma_tf32(float* c, const uint32_t* a, const uint32_t* b) {
    asm volatile(
        "mma.sync.aligned.m16n8k8.row.col.f32.tf32.tf32.f32 "
        "{%0,%1,%2,%3}, {%4,%5,%6,%7}, {%8,%9}, {%0,%1,%2,%3};"
        : "+f"(c[0]), "+f"(c[1]), "+f"(c[2]), "+f"(c[3])
        : "r"(a[0]), "r"(a[1]), "r"(a[2]), "r"(a[3]), "r"(b[0]), "r"(b[1]));
}

// ---------------------------------------------------------------------------
// tf32 pre-round
// ---------------------------------------------------------------------------
__global__ __launch_bounds__(256) void round_tf32(const float* __restrict__ in,
                                                  float* __restrict__ out, int n4)
{
    int i = blockIdx.x * 256 + threadIdx.x;
    if (i < n4) {
        float4 v = ((const float4*)in)[i];
        v.x = f2tf_f(v.x); v.y = f2tf_f(v.y);
        v.z = f2tf_f(v.z); v.w = f2tf_f(v.w);
        ((float4*)out)[i] = v;
    }
}

// ---------------------------------------------------------------------------
// tf32 mma.sync GEMM (unchanged from R7): C = A @ W^T + bias (+Res)(ReLU)(rnd)
// ---------------------------------------------------------------------------
#define BKg 32
#define NSTG 3
#define ROWPAD 36
#define TILE_FL (128 * ROWPAD)
#define STAGE_FL (2 * TILE_FL)
#define STAGE_BY (STAGE_FL * 4)
#define GSMEM (NSTG * STAGE_BY)                 // 110592 B

__device__ __forceinline__ void load_tiles_g(
    const float* __restrict__ A, const float* __restrict__ W, int K,
    int m0, int n0, int kc, uint32_t sbase, int tid)
{
#pragma unroll
    for (int i = 0; i < 8; i++) {
        int idx = tid + i * 128;
        int r = idx >> 3, q = idx & 7;
        cp16(sbase + r * (ROWPAD * 4) + q * 16,
             A + (size_t)(m0 + r) * K + kc + q * 4);
    }
#pragma unroll
    for (int i = 0; i < 8; i++) {
        int idx = tid + i * 128;
        int r = idx >> 3, q = idx & 7;
        cp16(sbase + TILE_FL * 4 + r * (ROWPAD * 4) + q * 16,
             W + (size_t)(n0 + r) * K + kc + q * 4);
    }
}

template<bool ADD_RES, bool RELU, bool ROUND_OUT>
__global__ __launch_bounds__(128, 2) void mma_gemm(
    const float* __restrict__ A, const float* __restrict__ W,
    const float* __restrict__ bias, const float* __restrict__ Res,
    float* __restrict__ C, int M, int N, int K)
{
    extern __shared__ float smf[];
    const uint32_t sb = smem_u32(smf);
    const int tid = threadIdx.x;
    const int wid = tid >> 5, lid = tid & 31;
    const int wm = wid & 1, wn = wid >> 1;
    const int g = lid >> 2, tg = lid & 3;
    const int m0 = blockIdx.y * 128, n0 = blockIdx.x * 128;

    float acc[4][8][4];
#pragma unroll
    for (int i = 0; i < 4; i++)
#pragma unroll
        for (int j = 0; j < 8; j++)
#pragma unroll
            for (int v = 0; v < 4; v++) acc[i][j][v] = 0.f;

    const int NC = K / BKg;
#pragma unroll
    for (int s = 0; s < NSTG; s++) {
        load_tiles_g(A, W, K, m0, n0, s * BKg, sb + s * STAGE_BY, tid);
        asm volatile("cp.async.commit_group;" ::: "memory");
    }

    for (int c = 0; c < NC; c++) {
        const int s = c % NSTG;
        asm volatile("cp.async.wait_group %0;" :: "n"(NSTG - 1) : "memory");
        __syncthreads();
        const uint32_t* As = (const uint32_t*)(smf + s * STAGE_FL);
        const uint32_t* Ws = As + TILE_FL;

#pragma unroll
        for (int kk = 0; kk < 4; kk++) {
            const int k0 = kk * 8;
            uint32_t af[4][4];
#pragma unroll
            for (int i = 0; i < 4; i++) {
                int rb = wm * 64 + i * 16 + g;
                af[i][0] = As[rb * ROWPAD + k0 + tg];
                af[i][1] = As[(rb + 8) * ROWPAD + k0 + tg];
                af[i][2] = As[rb * ROWPAD + k0 + tg + 4];
                af[i][3] = As[(rb + 8) * ROWPAD + k0 + tg + 4];
            }
            uint32_t bf[8][2];
#pragma unroll
            for (int j = 0; j < 8; j++) {
                int nb = wn * 64 + j * 8 + g;
                bf[j][0] = Ws[nb * ROWPAD + k0 + tg];
                bf[j][1] = Ws[nb * ROWPAD + k0 + tg + 4];
            }
#pragma unroll
            for (int i = 0; i < 4; i++)
#pragma unroll
                for (int j = 0; j < 8; j++)
                    mma_tf32(acc[i][j], af[i], bf[j]);
        }
        __syncthreads();
        if (c + NSTG < NC) {
            load_tiles_g(A, W, K, m0, n0, (c + NSTG) * BKg, sb + s * STAGE_BY, tid);
        }
        asm volatile("cp.async.commit_group;" ::: "memory");
    }

#pragma unroll
    for (int i = 0; i < 4; i++) {
#pragma unroll
        for (int r = 0; r < 2; r++) {
            const size_t row = (size_t)(m0 + wm * 64 + i * 16 + g + r * 8);
#pragma unroll
            for (int j = 0; j < 8; j++) {
                const int col = n0 + wn * 64 + j * 8 + tg * 2;
                float2 o;
                o.x = acc[i][j][r * 2 + 0];
                o.y = acc[i][j][r * 2 + 1];
                const float2 bb = *(const float2*)(bias + col);
                o.x += bb.x; o.y += bb.y;
                if (ADD_RES) {
                    float2 rr = *(const float2*)(Res + row * N + col);
                    o.x += rr.x; o.y += rr.y;
                }
                if (RELU) { o.x = fmaxf(o.x, 0.f); o.y = fmaxf(o.y, 0.f); }
                if (ROUND_OUT) { o.x = f2tf_f(o.x); o.y = f2tf_f(o.y); }
                *(float2*)(C + row * N + col) = o;
            }
        }
    }
}

// ---------------------------------------------------------------------------
// Padding-mask parsing (unchanged)
// ---------------------------------------------------------------------------
__global__ void len_kernel(const unsigned char* __restrict__ raw)
{
    __shared__ int sh_off, sh_f32;
    const int tid = threadIdx.x;
    if (tid == 0) { sh_off = 0; sh_f32 = 0; }
    __syncthreads();
    int f_off = 0, f_f32 = 0;
    for (int i = tid; i < Bv * Tv; i += 256) {
        unsigned char c = raw[i];
        if (c) {
            if ((i & 3) == 3 && c == 0x3f) f_f32 = 1;
            else if ((i & 3) != 0) f_off = 1;
        }
    }
    if (f_off) atomicOr(&sh_off, 1);
    if (f_f32) atomicOr(&sh_f32, 1);
    __syncthreads();
    const bool byte_mode = (sh_f32 == 0) && (sh_off != 0);
    const int w = tid >> 5, lane = tid & 31;
    if (w < Bv) {
        int cnt = 0;
        for (int t = lane; t < Tv; t += 32) {
            int m;
            if (byte_mode) m = (int)raw[w * Tv + t];
            else           m = ((const int*)raw)[w * Tv + t];
            cnt += (m == 0) ? 1 : 0;
        }
#pragma unroll
        for (int off = 16; off > 0; off >>= 1)
            cnt += __shfl_xor_sync(0xffffffffu, cnt, off);
        if (lane == 0) g_len[w] = cnt;
    }
}

// ---------------------------------------------------------------------------
// Tensor-core flash attention.
// Block = (64-q-tile, h, b), 128 threads / 4 warps; warp w owns q rows
// [w*16, w*16+16). Q frags register-resident; K/V double-buffered cp.async;
// online softmax in registers; P via per-warp-private smem (syncwarp only).
// Inputs (g_qkv) are pre-rounded tf32 by the QKV GEMM epilogue.
// smem pitches: 68 for A-pattern tiles (bank=4g+tg), 72 for V (bank=8tg+g).
// ---------------------------------------------------------------------------
#define AQ_OFF 0
#define AK_OFF (64 * 68)
#define AV_OFF (AK_OFF + 2 * 64 * 68)
#define AP_OFF (AV_OFF + 2 * 64 * 72)
#define ATT_FL (AP_OFF + 64 * 68)
#define ATT_SMEM (ATT_FL * 4)                   // 106496 B

__global__ __launch_bounds__(128, 2) void attn_kernel(const float* __restrict__ qkv,
                                                      float* __restrict__ out)
{
    extern __shared__ float sm[];
    const uint32_t sb = smem_u32(sm);
    const int b = blockIdx.z, h = blockIdx.y, qt = blockIdx.x;
    const int tid = threadIdx.x;
    const int wid = tid >> 5, lid = tid & 31;
    const int g = lid >> 2, tg = lid & 3;
    const int len = g_len[b];
    const int q0 = qt * 64;
    const int wrow = wid * 16;
    const size_t base = (size_t)b * Tv * (3 * Ev);

    // Load Q tile (scaled by 0.125 — exact pow2, stays tf32) into smem
#pragma unroll
    for (int i = 0; i < 8; i++) {
        int idx = tid + i * 128;
        int r = idx >> 4, c4 = (idx & 15) << 2;
        float4 v = *(const float4*)(qkv + base + (size_t)(q0 + r) * (3 * Ev) + h * HDv + c4);
        sm[AQ_OFF + r * 68 + c4 + 0] = v.x * 0.125f;
        sm[AQ_OFF + r * 68 + c4 + 1] = v.y * 0.125f;
        sm[AQ_OFF + r * 68 + c4 + 2] = v.z * 0.125f;
        sm[AQ_OFF + r * 68 + c4 + 3] = v.w * 0.125f;
    }

    const int ktend = min(qt, (len + 63) / 64 - 1);

    // Prefetch tile 0 (K rows token-major pitch 68; V token-major pitch 72)
    {
        const size_t kb = base + (size_t)0 * (3 * Ev) + h * HDv;
#pragma unroll
        for (int i = 0; i < 8; i++) {
            int idx = tid + i * 128;
            int r = idx >> 4, c4 = (idx & 15) << 2;
            cp16(sb + (AK_OFF + r * 68 + c4) * 4, qkv + kb + (size_t)r * (3 * Ev) + Ev + c4);
            cp16(sb + (AV_OFF + r * 72 + c4) * 4, qkv + kb + (size_t)r * (3 * Ev) + 2 * Ev + c4);
        }
        asm volatile("cp.async.commit_group;" ::: "memory");
    }
    __syncthreads();   // Qs visible

    // Q fragments: 8 k-steps x 4 regs
    uint32_t qf[8][4];
#pragma unroll
    for (int ks = 0; ks < 8; ks++) {
        const uint32_t* Qs = (const uint32_t*)(sm + AQ_OFF);
        qf[ks][0] = Qs[(wrow + g) * 68 + ks * 8 + tg];
        qf[ks][1] = Qs[(wrow + g + 8) * 68 + ks * 8 + tg];
        qf[ks][2] = Qs[(wrow + g) * 68 + ks * 8 + tg + 4];
        qf[ks][3] = Qs[(wrow + g + 8) * 68 + ks * 8 + tg + 4];
    }

    float of[8][4];
#pragma unroll
    for (int j = 0; j < 8; j++)
#pragma unroll
        for (int v = 0; v < 4; v++) of[j][v] = 0.f;
    float m0r = -1e30f, m1r = -1e30f, l0 = 0.f, l1 = 0.f;

    const int qg0 = q0 + wrow + g, qg1 = qg0 + 8;

    for (int kt = 0; kt <= ktend; kt++) {
        const int s = kt & 1;
        if (kt < ktend) {
            const size_t kb = base + (size_t)(kt + 1) * 64 * (3 * Ev) + h * HDv;
            const int s2 = (kt + 1) & 1;
#pragma unroll
            for (int i = 0; i < 8; i++) {
                int idx = tid + i * 128;
                int r = idx >> 4, c4 = (idx & 15) << 2;
                cp16(sb + (AK_OFF + s2 * 64 * 68 + r * 68 + c4) * 4,
                     qkv + kb + (size_t)r * (3 * Ev) + Ev + c4);
                cp16(sb + (AV_OFF + s2 * 64 * 72 + r * 72 + c4) * 4,
                     qkv + kb + (size_t)r * (3 * Ev) + 2 * Ev + c4);
            }
            asm volatile("cp.async.commit_group;" ::: "memory");
            asm volatile("cp.async.wait_group 1;" ::: "memory");
        } else {
            asm volatile("cp.async.wait_group 0;" ::: "memory");
        }
        __syncthreads();

        const uint32_t* Kst = (const uint32_t*)(sm + AK_OFF + s * 64 * 68);
        const uint32_t* Vst = (const uint32_t*)(sm + AV_OFF + s * 64 * 72);
        const int ktb = kt * 64;

        // S = Q K^T : per warp 16x64
        float sf[8][4];
#pragma unroll
        for (int j = 0; j < 8; j++) {
#pragma unroll
            for (int v = 0; v < 4; v++) sf[j][v] = 0.f;
#pragma unroll
            for (int ks = 0; ks < 8; ks++) {
                uint32_t bf[2];
                bf[0] = Kst[(j * 8 + g) * 68 + ks * 8 + tg];
                bf[1] = Kst[(j * 8 + g) * 68 + ks * 8 + tg + 4];
                mma_tf32(sf[j], qf[ks], bf);
            }
        }

        // Mask (causal + key padding)
#pragma unroll
        for (int j = 0; j < 8; j++) {
            int k0g = ktb + j * 8 + tg * 2;
            int k1g = k0g + 1;
            if (k0g > qg0 || k0g >= len) sf[j][0] = -1e30f;
            if (k1g > qg0 || k1g >= len) sf[j][1] = -1e30f;
            if (k0g > qg1 || k0g >= len) sf[j][2] = -1e30f;
            if (k1g > qg1 || k1g >= len) sf[j][3] = -1e30f;
        }

        // Online softmax (rows g / g+8; reduce across tg-quad)
        float mx0 = -1e30f, mx1 = -1e30f;
#pragma unroll
        for (int j = 0; j < 8; j++) {
            mx0 = fmaxf(mx0, fmaxf(sf[j][0], sf[j][1]));
            mx1 = fmaxf(mx1, fmaxf(sf[j][2], sf[j][3]));
        }
        mx0 = fmaxf(mx0, __shfl_xor_sync(0xffffffffu, mx0, 1));
        mx0 = fmaxf(mx0, __shfl_xor_sync(0xffffffffu, mx0, 2));
        mx1 = fmaxf(mx1, __shfl_xor_sync(0xffffffffu, mx1, 1));
        mx1 = fmaxf(mx1, __shfl_xor_sync(0xffffffffu, mx1, 2));
        const float mn0 = fmaxf(m0r, mx0), mn1 = fmaxf(m1r, mx1);
        const float scl0 = __expf(m0r - mn0), scl1 = __expf(m1r - mn1);
        float rs0 = 0.f, rs1 = 0.f;
#pragma unroll
        for (int j = 0; j < 8; j++) {
            sf[j][0] = __expf(sf[j][0] - mn0);
            sf[j][1] = __expf(sf[j][1] - mn0);
            sf[j][2] = __expf(sf[j][2] - mn1);
            sf[j][3] = __expf(sf[j][3] - mn1);
            rs0 += sf[j][0] + sf[j][1];
            rs1 += sf[j][2] + sf[j][3];
        }
        rs0 += __shfl_xor_sync(0xffffffffu, rs0, 1);
        rs0 += __shfl_xor_sync(0xffffffffu, rs0, 2);
        rs1 += __shfl_xor_sync(0xffffffffu, rs1, 1);
        rs1 += __shfl_xor_sync(0xffffffffu, rs1, 2);
        l0 = l0 * scl0 + rs0;  m0r = mn0;
        l1 = l1 * scl1 + rs1;  m1r = mn1;
#pragma unroll
        for (int j = 0; j < 8; j++) {
            of[j][0] *= scl0; of[j][1] *= scl0;
            of[j][2] *= scl1; of[j][3] *= scl1;
        }

        // P -> per-warp-private smem (tf32-rounded)
        float* Ps = sm + AP_OFF;
#pragma unroll
        for (int j = 0; j < 8; j++) {
            *(float2*)&Ps[(wrow + g) * 68 + j * 8 + tg * 2] =
                make_float2(f2tf_f(sf[j][0]), f2tf_f(sf[j][1]));
            *(float2*)&Ps[(wrow + g + 8) * 68 + j * 8 + tg * 2] =
                make_float2(f2tf_f(sf[j][2]), f2tf_f(sf[j][3]));
        }
        __syncwarp();

        // O += P V : A frags from Ps, B frags from Vst
        const uint32_t* Pu = (const uint32_t*)(sm + AP_OFF);
#pragma unroll
        for (int ks = 0; ks < 8; ks++) {
            uint32_t pa[4];
            pa[0] = Pu[(wrow + g) * 68 + ks * 8 + tg];
            pa[1] = Pu[(wrow + g + 8) * 68 + ks * 8 + tg];
            pa[2] = Pu[(wrow + g) * 68 + ks * 8 + tg + 4];
            pa[3] = Pu[(wrow + g + 8) * 68 + ks * 8 + tg + 4];
#pragma unroll
            for (int j = 0; j < 8; j++) {
                uint32_t bf[2];
                bf[0] = Vst[(ks * 8 + tg) * 72 + j * 8 + g];
                bf[1] = Vst[(ks * 8 + tg + 4) * 72 + j * 8 + g];
                mma_tf32(of[j], pa, bf);
            }
        }
        __syncthreads();   // stage reuse guard before next prefetch
    }

    // Normalize + write (tf32-rounded: feeds out-proj GEMM as A)
    const float inv0 = 1.f / l0, inv1 = 1.f / l1;
    const size_t row0 = (size_t)b * Tv + qg0;
    const size_t row1 = (size_t)b * Tv + qg1;
#pragma unroll
    for (int j = 0; j < 8; j++) {
        const int col = h * HDv + j * 8 + tg * 2;
        *(float2*)(out + row0 * Ev + col) =
            make_float2(f2tf_f(of[j][0] * inv0), f2tf_f(of[j][1] * inv0));
        *(float2*)(out + row1 * Ev + col) =
            make_float2(f2tf_f(of[j][2] * inv1), f2tf_f(of[j][3] * inv1));
    }
}

// ---------------------------------------------------------------------------
// LayerNorm; optionally emits a second tf32-rounded copy (GEMM A input)
// ---------------------------------------------------------------------------
template<bool DUAL>
__global__ __launch_bounds__(256) void ln_kernel(const float* __restrict__ X,
                                                 const float* __restrict__ w,
                                                 const float* __restrict__ bvec,
                                                 float* __restrict__ out,
                                                 float* __restrict__ out_r)
{
    const int row = blockIdx.x;
    const int tid = threadIdx.x;
    const float4 v = *(const float4*)(X + (long)row * Ev + tid * 4);
    float s = v.x + v.y + v.z + v.w;
    float q = v.x * v.x + v.y * v.y + v.z * v.z + v.w * v.w;
#pragma unroll
    for (int off = 16; off > 0; off >>= 1) {
        s += __shfl_xor_sync(0xffffffffu, s, off);
        q += __shfl_xor_sync(0xffffffffu, q, off);
    }
    __shared__ float red[16];
    __shared__ float sh_u, sh_r;
    const int wid = tid >> 5, lane = tid & 31;
    if (lane == 0) { red[wid] = s; red[8 + wid] = q; }
    __syncthreads();
    if (tid == 0) {
        float S = 0.f, Q = 0.f;
#pragma unroll
        for (int i = 0; i < 8; i++) { S += red[i]; Q += red[8 + i]; }
        float u = S * (1.f / 1024.f);
        float var = fmaxf(Q * (1.f / 1024.f) - u * u, 0.f);
        sh_u = u;
        sh_r = rsqrtf(var + 1e-12f);
    }
    __syncthreads();
    const float u = sh_u, rstd = sh_r;
    float4 ww = *(const float4*)(w + tid * 4);
    float4 bb = *(const float4*)(bvec + tid * 4);
    float4 o;
    o.x = (v.x - u) * rstd * ww.x + bb.x;
    o.y = (v.y - u) * rstd * ww.y + bb.y;
    o.z = (v.z - u) * rstd * ww.z + bb.z;
    o.w = (v.w - u) * rstd * ww.w + bb.w;
    *(float4*)(out + (long)row * Ev + tid * 4) = o;
    if (DUAL) {
        float4 r = make_float4(f2tf_f(o.x), f2tf_f(o.y), f2tf_f(o.z), f2tf_f(o.w));
        *(float4*)(out_r + (long)row * Ev + tid * 4) = r;
    }
}

// ---------------------------------------------------------------------------
// Launch
// ---------------------------------------------------------------------------
extern "C" void kernel_launch(void* const* d_in, const int* in_sizes, int n_in,
                              void* d_out, int out_size)
{
    const float* x     = (const float*)d_in[0];
    const float* in_w  = (const float*)d_in[1];
    const float* in_b  = (const float*)d_in[2];
    const float* out_w = (const float*)d_in[3];
    const float* out_b = (const float*)d_in[4];
    const float* fc1_w = (const float*)d_in[5];
    const float* fc1_b = (const float*)d_in[6];
    const float* fc2_w = (const float*)d_in[7];
    const float* fc2_b = (const float*)d_in[8];
    const float* ln1_w = (const float*)d_in[9];
    const float* ln1_b = (const float*)d_in[10];
    const float* ln2_w = (const float*)d_in[11];
    const float* ln2_b = (const float*)d_in[12];

    const unsigned char* pmask = (const unsigned char*)d_in[13];
    for (int i = 0; i < n_in; i++)
        if (in_sizes[i] == Bv * Tv) { pmask = (const unsigned char*)d_in[i]; break; }

    float *qkv, *attn, *y1, *x1, *x1r, *hb, *y2, *xr, *wq, *wo, *w1, *w2;
    cudaGetSymbolAddress((void**)&qkv,  g_qkv);
    cudaGetSymbolAddress((void**)&attn, g_attn);
    cudaGetSymbolAddress((void**)&y1,   g_y1);
    cudaGetSymbolAddress((void**)&x1,   g_x1);
    cudaGetSymbolAddress((void**)&x1r,  g_x1r);
    cudaGetSymbolAddress((void**)&hb,   g_h);
    cudaGetSymbolAddress((void**)&y2,   g_y2);
    cudaGetSymbolAddress((void**)&xr,   g_xr);
    cudaGetSymbolAddress((void**)&wq,   g_wq);
    cudaGetSymbolAddress((void**)&wo,   g_wo);
    cudaGetSymbolAddress((void**)&w1,   g_w1);
    cudaGetSymbolAddress((void**)&w2,   g_w2);

    cudaFuncSetAttribute(attn_kernel, cudaFuncAttributeMaxDynamicSharedMemorySize, ATT_SMEM);
    cudaFuncSetAttribute(mma_gemm<false, false, true >, cudaFuncAttributeMaxDynamicSharedMemorySize, GSMEM);
    cudaFuncSetAttribute(mma_gemm<true,  false, false>, cudaFuncAttributeMaxDynamicSharedMemorySize, GSMEM);
    cudaFuncSetAttribute(mma_gemm<false, true,  true >, cudaFuncAttributeMaxDynamicSharedMemorySize, GSMEM);

    len_kernel<<<1, 256>>>(pmask);

    // tf32 pre-rounding (exact rna, once per element)
    round_tf32<<<(Mv * Ev / 4 + 255) / 256, 256>>>(x, xr, Mv * Ev / 4);
    round_tf32<<<(3 * Ev * Ev / 4 + 255) / 256, 256>>>(in_w, wq, 3 * Ev * Ev / 4);
    round_tf32<<<(Ev * Ev / 4 + 255) / 256, 256>>>(out_w, wo, Ev * Ev / 4);
    round_tf32<<<(FFv * Ev / 4 + 255) / 256, 256>>>(fc1_w, w1, FFv * Ev / 4);
    round_tf32<<<(Ev * FFv / 4 + 255) / 256, 256>>>(fc2_w, w2, Ev * FFv / 4);

    // QKV projection (output tf32-rounded: feeds tensor-core attention)
    mma_gemm<false, false, true><<<dim3(3 * Ev / 128, Mv / 128), 128, GSMEM>>>(
        xr, wq, in_b, nullptr, qkv, Mv, 3 * Ev, Ev);

    // Tensor-core flash attention (causal + key padding); output tf32-rounded
    attn_kernel<<<dim3(Tv / 64, Hv, Bv), 128, ATT_SMEM>>>(qkv, attn);

    // Out projection + residual (residual = exact x)
    mma_gemm<true, false, false><<<dim3(Ev / 128, Mv / 128), 128, GSMEM>>>(
        attn, wo, out_b, x, y1, Mv, Ev, Ev);
    ln_kernel<true><<<Mv, 256>>>(y1, ln1_w, ln1_b, x1, x1r);

    // FFN
    mma_gemm<false, true, true><<<dim3(FFv / 128, Mv / 128), 128, GSMEM>>>(
        x1r, w1, fc1_b, nullptr, hb, Mv, FFv, Ev);
    mma_gemm<true, false, false><<<dim3(Ev / 128, Mv / 128), 128, GSMEM>>>(
        hb, w2, fc2_b, x1, y2, Mv, Ev, FFv);
    ln_kernel<false><<<Mv, 256>>>(y2, ln2_w, ln2_b, (float*)d_out, nullptr);

    (void)in_sizes; (void)n_in; (void)out_size;
}